// round 1
// baseline (speedup 1.0000x reference)
#include <cuda_runtime.h>
#include <math.h>

#define D_MODEL 1024
#define N_HEADS 16
#define D_K 64
#define BATCH 2
#define SEQ 2048
#define M_TOTAL (BATCH * SEQ)   // 4096

// ---------------- scratch (device globals: no allocation) ----------------
__device__ float g_Q[M_TOTAL * D_MODEL];
__device__ float g_K[M_TOTAL * D_MODEL];
__device__ float g_V[M_TOTAL * D_MODEL];
__device__ float g_X[M_TOTAL * D_MODEL];   // attention output (pre-Wo)

// ---------------- GEMM: C[m,n] = sum_k A[m,k]*B[n,k] + bias[n] ----------------
// A: M x K row-major, B: N x K row-major (i.e. torch Linear weight [out,in]).
// Tile 64x64, BK=16, 256 threads, 4x4 micro-tile per thread.
__global__ void __launch_bounds__(256) gemm_nt_kernel(
    const float* __restrict__ A, const float* __restrict__ B,
    const float* __restrict__ bias, float* __restrict__ C,
    int M, int N, int K)
{
    __shared__ float As[16][64];
    __shared__ float Bs[16][64];

    const int tid = threadIdx.x;
    const int bm = blockIdx.y * 64;
    const int bn = blockIdx.x * 64;
    const int tx = tid & 15;        // 0..15 -> n micro
    const int ty = tid >> 4;        // 0..15 -> m micro
    const int lr = tid >> 2;        // 0..63 row for loading
    const int lk = (tid & 3) * 4;   // k offset 0,4,8,12

    float acc[4][4] = {};

    const float* Aload = A + (size_t)(bm + lr) * K + lk;
    const float* Bload = B + (size_t)(bn + lr) * K + lk;

    for (int kt = 0; kt < K; kt += 16) {
        float4 a4 = *(const float4*)(Aload + kt);
        float4 b4 = *(const float4*)(Bload + kt);
        As[lk + 0][lr] = a4.x; As[lk + 1][lr] = a4.y;
        As[lk + 2][lr] = a4.z; As[lk + 3][lr] = a4.w;
        Bs[lk + 0][lr] = b4.x; Bs[lk + 1][lr] = b4.y;
        Bs[lk + 2][lr] = b4.z; Bs[lk + 3][lr] = b4.w;
        __syncthreads();

        #pragma unroll
        for (int k = 0; k < 16; k++) {
            float4 ar = *(const float4*)&As[k][ty * 4];
            float4 br = *(const float4*)&Bs[k][tx * 4];
            float a[4] = {ar.x, ar.y, ar.z, ar.w};
            float b[4] = {br.x, br.y, br.z, br.w};
            #pragma unroll
            for (int i = 0; i < 4; i++)
                #pragma unroll
                for (int j = 0; j < 4; j++)
                    acc[i][j] += a[i] * b[j];
        }
        __syncthreads();
    }

    float4 bi = *(const float4*)&bias[bn + tx * 4];
    float bj[4] = {bi.x, bi.y, bi.z, bi.w};
    #pragma unroll
    for (int i = 0; i < 4; i++) {
        float4 out;
        out.x = acc[i][0] + bj[0];
        out.y = acc[i][1] + bj[1];
        out.z = acc[i][2] + bj[2];
        out.w = acc[i][3] + bj[3];
        *(float4*)&C[(size_t)(bm + ty * 4 + i) * N + bn + tx * 4] = out;
    }
}

// ---------------- Flash attention ----------------
// grid: (SEQ/64, N_HEADS, BATCH), block: 64 threads.
// Each thread owns one q row: q[64], O[64], s[64] in registers.
__global__ void __launch_bounds__(64) flash_attn_kernel(
    const float* __restrict__ Q, const float* __restrict__ K,
    const float* __restrict__ V, float* __restrict__ X)
{
    __shared__ float Ks[64][64];
    __shared__ float Vs[64][64];

    const int tid = threadIdx.x;
    const int qb  = blockIdx.x;      // q tile
    const int h   = blockIdx.y;
    const int b   = blockIdx.z;
    const float scale = 0.125f;      // 1/sqrt(64)

    const int row = qb * 64 + tid;                      // q row within sequence
    const size_t qoff = ((size_t)(b * SEQ + row)) * D_MODEL + h * D_K;

    float q[64];
    #pragma unroll
    for (int d4 = 0; d4 < 16; d4++) {
        float4 t = *(const float4*)(Q + qoff + d4 * 4);
        q[d4 * 4 + 0] = t.x; q[d4 * 4 + 1] = t.y;
        q[d4 * 4 + 2] = t.z; q[d4 * 4 + 3] = t.w;
    }

    float O[64];
    #pragma unroll
    for (int d = 0; d < 64; d++) O[d] = 0.0f;
    float m = -INFINITY, l = 0.0f;

    const size_t kvbase = ((size_t)(b * SEQ)) * D_MODEL + h * D_K;

    for (int kt = 0; kt < SEQ / 64; kt++) {
        // cooperative tile load: thread tid loads row tid of the K/V tile
        const size_t src = kvbase + ((size_t)(kt * 64 + tid)) * D_MODEL;
        #pragma unroll
        for (int d4 = 0; d4 < 16; d4++) {
            *(float4*)&Ks[tid][d4 * 4] = *(const float4*)(K + src + d4 * 4);
            *(float4*)&Vs[tid][d4 * 4] = *(const float4*)(V + src + d4 * 4);
        }
        __syncthreads();

        // pass 1: scores for all 64 keys
        float s[64];
        #pragma unroll
        for (int kj = 0; kj < 64; kj++) {
            float acc = 0.0f;
            #pragma unroll
            for (int d4 = 0; d4 < 16; d4++) {
                float4 kv = *(const float4*)&Ks[kj][d4 * 4];
                acc += q[d4 * 4 + 0] * kv.x;
                acc += q[d4 * 4 + 1] * kv.y;
                acc += q[d4 * 4 + 2] * kv.z;
                acc += q[d4 * 4 + 3] * kv.w;
            }
            s[kj] = acc * scale;
        }

        // online softmax update (one correction per tile)
        float tmax = s[0];
        #pragma unroll
        for (int kj = 1; kj < 64; kj++) tmax = fmaxf(tmax, s[kj]);
        float m_new = fmaxf(m, tmax);
        float corr = __expf(m - m_new);   // m=-inf first iter -> 0

        float psum = 0.0f;
        #pragma unroll
        for (int kj = 0; kj < 64; kj++) {
            s[kj] = __expf(s[kj] - m_new);
            psum += s[kj];
        }
        l = l * corr + psum;
        m = m_new;

        #pragma unroll
        for (int d = 0; d < 64; d++) O[d] *= corr;

        // pass 2: O += P * V
        #pragma unroll
        for (int kj = 0; kj < 64; kj++) {
            float p = s[kj];
            #pragma unroll
            for (int d4 = 0; d4 < 16; d4++) {
                float4 vv = *(const float4*)&Vs[kj][d4 * 4];
                O[d4 * 4 + 0] += p * vv.x;
                O[d4 * 4 + 1] += p * vv.y;
                O[d4 * 4 + 2] += p * vv.z;
                O[d4 * 4 + 3] += p * vv.w;
            }
        }
        __syncthreads();
    }

    const float inv_l = 1.0f / l;
    #pragma unroll
    for (int d4 = 0; d4 < 16; d4++) {
        float4 out;
        out.x = O[d4 * 4 + 0] * inv_l;
        out.y = O[d4 * 4 + 1] * inv_l;
        out.z = O[d4 * 4 + 2] * inv_l;
        out.w = O[d4 * 4 + 3] * inv_l;
        *(float4*)&g_X[qoff + d4 * 4] = out;
    }
}

// ---------------- launch ----------------
extern "C" void kernel_launch(void* const* d_in, const int* in_sizes, int n_in,
                              void* d_out, int out_size)
{
    const float* q  = (const float*)d_in[0];
    const float* k  = (const float*)d_in[1];
    const float* v  = (const float*)d_in[2];
    const float* Wq = (const float*)d_in[3];
    const float* bq = (const float*)d_in[4];
    const float* Wk = (const float*)d_in[5];
    const float* bk = (const float*)d_in[6];
    const float* Wv = (const float*)d_in[7];
    const float* bv = (const float*)d_in[8];
    const float* Wo = (const float*)d_in[9];
    const float* bo = (const float*)d_in[10];
    float* out = (float*)d_out;

    float *gq, *gk, *gv, *gx;
    cudaGetSymbolAddress((void**)&gq, g_Q);
    cudaGetSymbolAddress((void**)&gk, g_K);
    cudaGetSymbolAddress((void**)&gv, g_V);
    cudaGetSymbolAddress((void**)&gx, g_X);

    dim3 gblock(256);
    dim3 ggrid(D_MODEL / 64, M_TOTAL / 64);   // (16, 64)

    gemm_nt_kernel<<<ggrid, gblock>>>(q, Wq, bq, gq, M_TOTAL, D_MODEL, D_MODEL);
    gemm_nt_kernel<<<ggrid, gblock>>>(k, Wk, bk, gk, M_TOTAL, D_MODEL, D_MODEL);
    gemm_nt_kernel<<<ggrid, gblock>>>(v, Wv, bv, gv, M_TOTAL, D_MODEL, D_MODEL);

    dim3 fgrid(SEQ / 64, N_HEADS, BATCH);     // (32, 16, 2)
    flash_attn_kernel<<<fgrid, 64>>>(gq, gk, gv, gx);

    gemm_nt_kernel<<<ggrid, gblock>>>(gx, Wo, bo, out, M_TOTAL, D_MODEL, D_MODEL);
}

// round 3
// speedup vs baseline: 2.1316x; 2.1316x over previous
#include <cuda_runtime.h>
#include <math.h>
#include <cstdint>

#define D_MODEL 1024
#define N_HEADS 16
#define D_K 64
#define BATCH 2
#define SEQ 2048
#define M_TOTAL (BATCH * SEQ)   // 4096

// ---------------- scratch (device globals: no allocation) ----------------
__device__ float g_qh[M_TOTAL * D_MODEL], g_ql[M_TOTAL * D_MODEL];
__device__ float g_kh[M_TOTAL * D_MODEL], g_kl[M_TOTAL * D_MODEL];
__device__ float g_vh[M_TOTAL * D_MODEL], g_vl[M_TOTAL * D_MODEL];
__device__ float g_Wqh[D_MODEL * D_MODEL], g_Wql[D_MODEL * D_MODEL];
__device__ float g_Wkh[D_MODEL * D_MODEL], g_Wkl[D_MODEL * D_MODEL];
__device__ float g_Wvh[D_MODEL * D_MODEL], g_Wvl[D_MODEL * D_MODEL];
__device__ float g_Woh[D_MODEL * D_MODEL], g_Wol[D_MODEL * D_MODEL];
__device__ float g_Q[M_TOTAL * D_MODEL];
__device__ float g_K[M_TOTAL * D_MODEL];
__device__ float g_V[M_TOTAL * D_MODEL];
__device__ float g_Xh[M_TOTAL * D_MODEL], g_Xl[M_TOTAL * D_MODEL];

// ---------------- helpers ----------------
__device__ __forceinline__ uint32_t smem_u32(const void* p) {
    uint32_t a;
    asm("{ .reg .u64 t; cvta.to.shared.u64 t, %1; cvt.u32.u64 %0, t; }" : "=r"(a) : "l"(p));
    return a;
}

__device__ __forceinline__ float tf32_rna(float x) {
    uint32_t u;
    asm("cvt.rna.tf32.f32 %0, %1;" : "=r"(u) : "f"(x));
    return __uint_as_float(u);
}

__device__ __forceinline__ void cp16(uint32_t s, const void* g) {
    asm volatile("cp.async.cg.shared.global [%0], [%1], 16;" :: "r"(s), "l"(g));
}
__device__ __forceinline__ void cp_commit() {
    asm volatile("cp.async.commit_group;" ::: "memory");
}
template <int N>
__device__ __forceinline__ void cp_wait() {
    asm volatile("cp.async.wait_group %0;" :: "n"(N) : "memory");
}

// D = A(16x8) * B(8x8) + D, tf32 inputs, fp32 accum
__device__ __forceinline__ void mma_tf32(float c[4], const float a[4], const float b[2]) {
    asm volatile(
        "mma.sync.aligned.m16n8k8.row.col.f32.tf32.tf32.f32 "
        "{%0,%1,%2,%3}, {%4,%5,%6,%7}, {%8,%9}, {%0,%1,%2,%3};"
        : "+f"(c[0]), "+f"(c[1]), "+f"(c[2]), "+f"(c[3])
        : "r"(__float_as_uint(a[0])), "r"(__float_as_uint(a[1])),
          "r"(__float_as_uint(a[2])), "r"(__float_as_uint(a[3])),
          "r"(__float_as_uint(b[0])), "r"(__float_as_uint(b[1])));
}

// ---------------- hi/lo split conversion ----------------
__global__ void __launch_bounds__(256) cvt_hilo_kernel(
    const float* __restrict__ in, float* __restrict__ hi, float* __restrict__ lo, int n4)
{
    int i = blockIdx.x * blockDim.x + threadIdx.x;
    int stride = gridDim.x * blockDim.x;
    for (; i < n4; i += stride) {
        float4 x = ((const float4*)in)[i];
        float4 h4, l4;
        h4.x = tf32_rna(x.x); l4.x = tf32_rna(x.x - h4.x);
        h4.y = tf32_rna(x.y); l4.y = tf32_rna(x.y - h4.y);
        h4.z = tf32_rna(x.z); l4.z = tf32_rna(x.z - h4.z);
        h4.w = tf32_rna(x.w); l4.w = tf32_rna(x.w - h4.w);
        ((float4*)hi)[i] = h4;
        ((float4*)lo)[i] = l4;
    }
}

// ---------------- 3xTF32 mma.sync GEMM: C = A*B^T + bias ----------------
// A: M x K (hi/lo), B: N x K (hi/lo), K-major row-major.
// CTA tile 128x128, K-chunk 32, 8 warps: warp tile 64(M) x 32(N).
// Smem tiles stride 36 floats/row (conflict-free: bank = lane).
#define KC 32
#define TSTRIDE 36
#define TILE_FLOATS (128 * TSTRIDE)
#define BUF_FLOATS (4 * TILE_FLOATS)
#define GEMM_SMEM (2 * BUF_FLOATS * 4)   // 147456 bytes

__global__ void __launch_bounds__(256, 1) gemm_tf32x3_kernel(
    const float* __restrict__ Ah, const float* __restrict__ Al,
    const float* __restrict__ Bh, const float* __restrict__ Bl,
    const float* __restrict__ bias, float* __restrict__ C,
    int M, int N, int K)
{
    extern __shared__ float sm[];
    const int tid = threadIdx.x;
    const int wid = tid >> 5, lane = tid & 31;
    const int g = lane >> 2, t4 = lane & 3;
    const int bm = blockIdx.y * 128;
    const int bn = blockIdx.x * 128;
    const int wm = (wid >> 2) * 64;      // 0 or 64
    const int wn = (wid & 3) * 32;       // 0,32,64,96

    const float* gsrc[4];
    gsrc[0] = Ah + (size_t)bm * K;
    gsrc[1] = Al + (size_t)bm * K;
    gsrc[2] = Bh + (size_t)bn * K;
    gsrc[3] = Bl + (size_t)bn * K;

    const uint32_t smb = smem_u32(sm);

    // staging addresses: unit u in 0..1023 per tile: row=u>>3, seg=u&7 (16B each)
    uint32_t sdst[2][4][4];
    const float* gbase[4][4];
    #pragma unroll
    for (int t = 0; t < 4; t++)
        #pragma unroll
        for (int j = 0; j < 4; j++) {
            int u = tid + 256 * j;
            int row = u >> 3, seg = u & 7;
            uint32_t off = (uint32_t)(t * TILE_FLOATS + row * TSTRIDE + seg * 4) * 4u;
            sdst[0][t][j] = smb + off;
            sdst[1][t][j] = smb + BUF_FLOATS * 4u + off;
            gbase[t][j] = gsrc[t] + (size_t)row * K + seg * 4;
        }

    float c[4][4][4];
    #pragma unroll
    for (int i = 0; i < 4; i++)
        #pragma unroll
        for (int j = 0; j < 4; j++)
            #pragma unroll
            for (int e = 0; e < 4; e++) c[i][j][e] = 0.f;

    const int nchunk = K / KC;

    // prologue: chunk 0 -> buf 0
    #pragma unroll
    for (int t = 0; t < 4; t++)
        #pragma unroll
        for (int j = 0; j < 4; j++)
            cp16(sdst[0][t][j], gbase[t][j]);
    cp_commit();

    for (int kt = 0; kt < nchunk; kt++) {
        if (kt + 1 < nchunk) {
            int nb = (kt + 1) & 1;
            #pragma unroll
            for (int t = 0; t < 4; t++)
                #pragma unroll
                for (int j = 0; j < 4; j++)
                    cp16(sdst[nb][t][j], gbase[t][j] + (kt + 1) * KC);
            cp_commit();
            cp_wait<1>();
        } else {
            cp_wait<0>();
        }
        __syncthreads();

        const float* buf = sm + (kt & 1) * BUF_FLOATS;
        const float* sAh = buf;
        const float* sAl = buf + TILE_FLOATS;
        const float* sBh = buf + 2 * TILE_FLOATS;
        const float* sBl = buf + 3 * TILE_FLOATS;

        #pragma unroll
        for (int ks = 0; ks < 4; ks++) {
            const int k0 = ks * 8;
            float ah[4][4], al[4][4];
            #pragma unroll
            for (int i = 0; i < 4; i++) {
                int r = wm + 16 * i + g;
                ah[i][0] = sAh[r * TSTRIDE + k0 + t4];
                ah[i][1] = sAh[(r + 8) * TSTRIDE + k0 + t4];
                ah[i][2] = sAh[r * TSTRIDE + k0 + t4 + 4];
                ah[i][3] = sAh[(r + 8) * TSTRIDE + k0 + t4 + 4];
                al[i][0] = sAl[r * TSTRIDE + k0 + t4];
                al[i][1] = sAl[(r + 8) * TSTRIDE + k0 + t4];
                al[i][2] = sAl[r * TSTRIDE + k0 + t4 + 4];
                al[i][3] = sAl[(r + 8) * TSTRIDE + k0 + t4 + 4];
            }
            float bh[4][2], bl[4][2];
            #pragma unroll
            for (int j = 0; j < 4; j++) {
                int n = wn + 8 * j + g;
                bh[j][0] = sBh[n * TSTRIDE + k0 + t4];
                bh[j][1] = sBh[n * TSTRIDE + k0 + t4 + 4];
                bl[j][0] = sBl[n * TSTRIDE + k0 + t4];
                bl[j][1] = sBl[n * TSTRIDE + k0 + t4 + 4];
            }
            #pragma unroll
            for (int i = 0; i < 4; i++)
                #pragma unroll
                for (int j = 0; j < 4; j++) {
                    mma_tf32(c[i][j], ah[i], bh[j]);
                    mma_tf32(c[i][j], ah[i], bl[j]);
                    mma_tf32(c[i][j], al[i], bh[j]);
                }
        }
        __syncthreads();
    }

    // epilogue
    #pragma unroll
    for (int j = 0; j < 4; j++) {
        int col = bn + wn + 8 * j + 2 * t4;
        float b0 = bias[col], b1 = bias[col + 1];
        #pragma unroll
        for (int i = 0; i < 4; i++) {
            int row = bm + wm + 16 * i + g;
            float2 lo2 = make_float2(c[i][j][0] + b0, c[i][j][1] + b1);
            float2 hi2 = make_float2(c[i][j][2] + b0, c[i][j][3] + b1);
            *(float2*)&C[(size_t)row * N + col] = lo2;
            *(float2*)&C[(size_t)(row + 8) * N + col] = hi2;
        }
    }
}

// ---------------- attention (fp32, GEMM-style tiling) ----------------
#define AT_PAD 68
#define ATTN_SMEM ((3 * 64 * AT_PAD + 64 * 64) * 4)

__global__ void __launch_bounds__(256) attn_fp32_kernel(
    const float* __restrict__ Q, const float* __restrict__ K,
    const float* __restrict__ V, float* __restrict__ Xh, float* __restrict__ Xl)
{
    extern __shared__ float sf[];
    float* Qs = sf;
    float* Ks = sf + 64 * AT_PAD;
    float* Ps = sf + 2 * 64 * AT_PAD;
    float* Vs = sf + 3 * 64 * AT_PAD;

    const int tid = threadIdx.x;
    const int tx = tid & 15, ty = tid >> 4;
    const int qb = blockIdx.x, h = blockIdx.y, b = blockIdx.z;

    const size_t qrow0 = (size_t)b * SEQ + qb * 64;
    const size_t kbase = (size_t)b * SEQ;
    const int hoff = h * D_K;

    // load Q tile transposed: Qs[d][r]
    {
        const int d = tid & 63, r0 = tid >> 6;
        #pragma unroll
        for (int e = 0; e < 16; e++) {
            int rr = r0 * 16 + e;
            Qs[d * AT_PAD + rr] = Q[(qrow0 + rr) * D_MODEL + hoff + d];
        }
    }

    float s[4][4], O[4][4];
    float mr[4], lr[4];
    #pragma unroll
    for (int i = 0; i < 4; i++) {
        mr[i] = -1e30f; lr[i] = 0.f;
        #pragma unroll
        for (int j = 0; j < 4; j++) O[i][j] = 0.f;
    }

    for (int kt = 0; kt < SEQ / 64; kt++) {
        __syncthreads();
        {
            const int d = tid & 63, r0 = tid >> 6;
            #pragma unroll
            for (int e = 0; e < 16; e++) {
                int rr = r0 * 16 + e;
                Ks[d * AT_PAD + rr] = K[(kbase + kt * 64 + rr) * D_MODEL + hoff + d];
            }
        }
        {
            #pragma unroll
            for (int e = 0; e < 4; e++) {
                int vi = tid + 256 * e;
                int rr = vi >> 4, cc = (vi & 15) * 4;
                *(float4*)&Vs[rr * 64 + cc] =
                    *(const float4*)&V[(kbase + kt * 64 + rr) * D_MODEL + hoff + cc];
            }
        }
        __syncthreads();

        #pragma unroll
        for (int i = 0; i < 4; i++)
            #pragma unroll
            for (int j = 0; j < 4; j++) s[i][j] = 0.f;

        #pragma unroll 4
        for (int d = 0; d < 64; d++) {
            float4 qa = *(const float4*)&Qs[d * AT_PAD + ty * 4];
            float4 kb = *(const float4*)&Ks[d * AT_PAD + tx * 4];
            float ai[4] = {qa.x, qa.y, qa.z, qa.w};
            float bj[4] = {kb.x, kb.y, kb.z, kb.w};
            #pragma unroll
            for (int i = 0; i < 4; i++)
                #pragma unroll
                for (int j = 0; j < 4; j++)
                    s[i][j] += ai[i] * bj[j];
        }

        #pragma unroll
        for (int i = 0; i < 4; i++) {
            #pragma unroll
            for (int j = 0; j < 4; j++) s[i][j] *= 0.125f;
            float tm = fmaxf(fmaxf(s[i][0], s[i][1]), fmaxf(s[i][2], s[i][3]));
            #pragma unroll
            for (int mk = 1; mk < 16; mk <<= 1)
                tm = fmaxf(tm, __shfl_xor_sync(0xffffffffu, tm, mk));
            float mn = fmaxf(mr[i], tm);
            float corr = __expf(mr[i] - mn);
            float ps = 0.f;
            #pragma unroll
            for (int j = 0; j < 4; j++) {
                s[i][j] = __expf(s[i][j] - mn);
                ps += s[i][j];
            }
            #pragma unroll
            for (int mk = 1; mk < 16; mk <<= 1)
                ps += __shfl_xor_sync(0xffffffffu, ps, mk);
            lr[i] = lr[i] * corr + ps;
            mr[i] = mn;
            #pragma unroll
            for (int j = 0; j < 4; j++) O[i][j] *= corr;
        }

        #pragma unroll
        for (int i = 0; i < 4; i++)
            #pragma unroll
            for (int j = 0; j < 4; j++)
                Ps[(tx * 4 + j) * AT_PAD + ty * 4 + i] = s[i][j];
        __syncthreads();

        #pragma unroll 4
        for (int kk = 0; kk < 64; kk++) {
            float4 pa = *(const float4*)&Ps[kk * AT_PAD + ty * 4];
            float4 vb = *(const float4*)&Vs[kk * 64 + tx * 4];
            float pi[4] = {pa.x, pa.y, pa.z, pa.w};
            float vj[4] = {vb.x, vb.y, vb.z, vb.w};
            #pragma unroll
            for (int i = 0; i < 4; i++)
                #pragma unroll
                for (int j = 0; j < 4; j++)
                    O[i][j] += pi[i] * vj[j];
        }
    }

    #pragma unroll
    for (int i = 0; i < 4; i++) {
        float inv = 1.0f / lr[i];
        size_t off = (qrow0 + ty * 4 + i) * D_MODEL + hoff + tx * 4;
        float4 h4, l4;
        float v0 = O[i][0] * inv, v1 = O[i][1] * inv, v2 = O[i][2] * inv, v3 = O[i][3] * inv;
        h4.x = tf32_rna(v0); l4.x = tf32_rna(v0 - h4.x);
        h4.y = tf32_rna(v1); l4.y = tf32_rna(v1 - h4.y);
        h4.z = tf32_rna(v2); l4.z = tf32_rna(v2 - h4.z);
        h4.w = tf32_rna(v3); l4.w = tf32_rna(v3 - h4.w);
        *(float4*)&Xh[off] = h4;
        *(float4*)&Xl[off] = l4;
    }
}

// ---------------- launch ----------------
extern "C" void kernel_launch(void* const* d_in, const int* in_sizes, int n_in,
                              void* d_out, int out_size)
{
    const float* q  = (const float*)d_in[0];
    const float* k  = (const float*)d_in[1];
    const float* v  = (const float*)d_in[2];
    const float* Wq = (const float*)d_in[3];
    const float* bq = (const float*)d_in[4];
    const float* Wk = (const float*)d_in[5];
    const float* bk = (const float*)d_in[6];
    const float* Wv = (const float*)d_in[7];
    const float* bv = (const float*)d_in[8];
    const float* Wo = (const float*)d_in[9];
    const float* bo = (const float*)d_in[10];
    float* out = (float*)d_out;

    float *qh, *ql, *kh, *kl, *vh, *vl;
    float *Wqh, *Wql, *Wkh, *Wkl, *Wvh, *Wvl, *Woh, *Wol;
    float *Qp, *Kp, *Vp, *Xh, *Xl;
    cudaGetSymbolAddress((void**)&qh, g_qh);   cudaGetSymbolAddress((void**)&ql, g_ql);
    cudaGetSymbolAddress((void**)&kh, g_kh);   cudaGetSymbolAddress((void**)&kl, g_kl);
    cudaGetSymbolAddress((void**)&vh, g_vh);   cudaGetSymbolAddress((void**)&vl, g_vl);
    cudaGetSymbolAddress((void**)&Wqh, g_Wqh); cudaGetSymbolAddress((void**)&Wql, g_Wql);
    cudaGetSymbolAddress((void**)&Wkh, g_Wkh); cudaGetSymbolAddress((void**)&Wkl, g_Wkl);
    cudaGetSymbolAddress((void**)&Wvh, g_Wvh); cudaGetSymbolAddress((void**)&Wvl, g_Wvl);
    cudaGetSymbolAddress((void**)&Woh, g_Woh); cudaGetSymbolAddress((void**)&Wol, g_Wol);
    cudaGetSymbolAddress((void**)&Qp, g_Q);    cudaGetSymbolAddress((void**)&Kp, g_K);
    cudaGetSymbolAddress((void**)&Vp, g_V);
    cudaGetSymbolAddress((void**)&Xh, g_Xh);   cudaGetSymbolAddress((void**)&Xl, g_Xl);

    cudaFuncSetAttribute(gemm_tf32x3_kernel,
                         cudaFuncAttributeMaxDynamicSharedMemorySize, GEMM_SMEM);
    cudaFuncSetAttribute(attn_fp32_kernel,
                         cudaFuncAttributeMaxDynamicSharedMemorySize, ATTN_SMEM);

    const int nAct4 = M_TOTAL * D_MODEL / 4;
    const int nW4   = D_MODEL * D_MODEL / 4;

    cvt_hilo_kernel<<<1024, 256>>>(q,  qh,  ql,  nAct4);
    cvt_hilo_kernel<<<1024, 256>>>(k,  kh,  kl,  nAct4);
    cvt_hilo_kernel<<<1024, 256>>>(v,  vh,  vl,  nAct4);
    cvt_hilo_kernel<<<512,  256>>>(Wq, Wqh, Wql, nW4);
    cvt_hilo_kernel<<<512,  256>>>(Wk, Wkh, Wkl, nW4);
    cvt_hilo_kernel<<<512,  256>>>(Wv, Wvh, Wvl, nW4);
    cvt_hilo_kernel<<<512,  256>>>(Wo, Woh, Wol, nW4);

    dim3 ggrid(D_MODEL / 128, M_TOTAL / 128);   // (8, 32)
    gemm_tf32x3_kernel<<<ggrid, 256, GEMM_SMEM>>>(qh, ql, Wqh, Wql, bq, Qp,
                                                  M_TOTAL, D_MODEL, D_MODEL);
    gemm_tf32x3_kernel<<<ggrid, 256, GEMM_SMEM>>>(kh, kl, Wkh, Wkl, bk, Kp,
                                                  M_TOTAL, D_MODEL, D_MODEL);
    gemm_tf32x3_kernel<<<ggrid, 256, GEMM_SMEM>>>(vh, vl, Wvh, Wvl, bv, Vp,
                                                  M_TOTAL, D_MODEL, D_MODEL);

    dim3 agrid(SEQ / 64, N_HEADS, BATCH);       // (32, 16, 2)
    attn_fp32_kernel<<<agrid, 256, ATTN_SMEM>>>(Qp, Kp, Vp, Xh, Xl);

    gemm_tf32x3_kernel<<<ggrid, 256, GEMM_SMEM>>>(Xh, Xl, Woh, Wol, bo, out,
                                                  M_TOTAL, D_MODEL, D_MODEL);
}

// round 4
// speedup vs baseline: 4.3746x; 2.0522x over previous
#include <cuda_runtime.h>
#include <cuda_bf16.h>
#include <math.h>
#include <cstdint>

#define D_MODEL 1024
#define NH 16
#define DK 64
#define BATCH 2
#define SEQ 2048
#define MT (BATCH * SEQ)        // 4096
#define KU (D_MODEL / 2)        // 512 u32 (bf16 pairs) per row

// ---------------- scratch (device globals) ----------------
__device__ uint32_t g_qh[MT * KU],  g_ql[MT * KU];
__device__ uint32_t g_kh[MT * KU],  g_kl[MT * KU];
__device__ uint32_t g_vh[MT * KU],  g_vl[MT * KU];
__device__ uint32_t g_Wqh[D_MODEL * KU], g_Wql[D_MODEL * KU];
__device__ uint32_t g_Wkh[D_MODEL * KU], g_Wkl[D_MODEL * KU];
__device__ uint32_t g_Wvh[D_MODEL * KU], g_Wvl[D_MODEL * KU];
__device__ uint32_t g_Woh[D_MODEL * KU], g_Wol[D_MODEL * KU];
__device__ uint32_t g_Qh[MT * KU], g_Ql[MT * KU];
__device__ uint32_t g_Kh[MT * KU], g_Kl[MT * KU];
__device__ uint32_t g_Vh[MT * KU], g_Vl[MT * KU];
__device__ uint32_t g_Vth[BATCH * NH * DK * (SEQ / 2)], g_Vtl[BATCH * NH * DK * (SEQ / 2)];
__device__ uint32_t g_Xh[MT * KU], g_Xl[MT * KU];

// ---------------- helpers ----------------
__device__ __forceinline__ uint32_t smem_u32(const void* p) {
    uint32_t a;
    asm("{ .reg .u64 t; cvta.to.shared.u64 t, %1; cvt.u32.u64 %0, t; }" : "=r"(a) : "l"(p));
    return a;
}
__device__ __forceinline__ void cp16(uint32_t s, const void* g) {
    asm volatile("cp.async.cg.shared.global [%0], [%1], 16;" :: "r"(s), "l"(g));
}
__device__ __forceinline__ void cp_commit() {
    asm volatile("cp.async.commit_group;" ::: "memory");
}
template <int N>
__device__ __forceinline__ void cp_wait() {
    asm volatile("cp.async.wait_group %0;" :: "n"(N) : "memory");
}

// bf16x2 mma: D(16x8,f32) += A(16x16,bf16) * B(16x8,bf16)
__device__ __forceinline__ void mma_bf16(float c[4], const uint32_t a[4], const uint32_t b[2]) {
    asm volatile(
        "mma.sync.aligned.m16n8k16.row.col.f32.bf16.bf16.f32 "
        "{%0,%1,%2,%3}, {%4,%5,%6,%7}, {%8,%9}, {%0,%1,%2,%3};"
        : "+f"(c[0]), "+f"(c[1]), "+f"(c[2]), "+f"(c[3])
        : "r"(a[0]), "r"(a[1]), "r"(a[2]), "r"(a[3]), "r"(b[0]), "r"(b[1]));
}

// split two fp32 into packed bf16 hi-pair and lo-pair (v0 -> low 16 bits)
__device__ __forceinline__ void split2(float v0, float v1, uint32_t& hp, uint32_t& lp) {
    __nv_bfloat162 hh, ll;
    hh.x = __float2bfloat16_rn(v0);
    hh.y = __float2bfloat16_rn(v1);
    ll.x = __float2bfloat16_rn(v0 - __bfloat162float(hh.x));
    ll.y = __float2bfloat16_rn(v1 - __bfloat162float(hh.y));
    hp = *reinterpret_cast<uint32_t*>(&hh);
    lp = *reinterpret_cast<uint32_t*>(&ll);
}

// ---------------- fp32 -> bf16 hi/lo conversion ----------------
__global__ void __launch_bounds__(256) cvt_kernel(
    const float* __restrict__ in, uint32_t* __restrict__ h, uint32_t* __restrict__ l, int n4)
{
    int i = blockIdx.x * blockDim.x + threadIdx.x;
    int stride = gridDim.x * blockDim.x;
    for (; i < n4; i += stride) {
        float4 x = ((const float4*)in)[i];
        uint32_t h0, l0, h1, l1;
        split2(x.x, x.y, h0, l0);
        split2(x.z, x.w, h1, l1);
        ((uint2*)h)[i] = make_uint2(h0, h1);
        ((uint2*)l)[i] = make_uint2(l0, l1);
    }
}

// ---------------- bf16x3 GEMM: C = A*B^T + bias ----------------
// A: M x K, B: N x K (hi/lo bf16, pairs along K). CTA 128x128, kchunk 32.
// 8 warps, warp tile 64x32. mode 0: fp32 out; mode 1: bf16 hi/lo out.
#define GST 20                     // smem row stride (u32)
#define GTILE (128 * GST)          // 2560 u32 per tile
#define GBUF (4 * GTILE)           // Ah, Al, Bh, Bl
#define GEMM_SMEM (2 * GBUF * 4)   // 81920 B

__global__ void __launch_bounds__(256, 1) gemm_bf16x3_kernel(
    const uint32_t* __restrict__ Ah, const uint32_t* __restrict__ Al,
    const uint32_t* __restrict__ Bh, const uint32_t* __restrict__ Bl,
    const float* __restrict__ bias,
    float* __restrict__ Cf, uint32_t* __restrict__ Ch, uint32_t* __restrict__ Cl,
    int M, int N, int K, int mode)
{
    extern __shared__ uint32_t su[];
    const uint32_t smb = smem_u32(su);
    const int tid = threadIdx.x;
    const int wid = tid >> 5, lane = tid & 31;
    const int g = lane >> 2, t4 = lane & 3;
    const int bm = blockIdx.y * 128, bn = blockIdx.x * 128;
    const int wm = (wid >> 2) * 64, wn = (wid & 3) * 32;
    const int KW = K >> 1;

    const uint32_t* gt[4];
    gt[0] = Ah + (size_t)bm * KW;
    gt[1] = Al + (size_t)bm * KW;
    gt[2] = Bh + (size_t)bn * KW;
    gt[3] = Bl + (size_t)bn * KW;

    float c[4][4][4];
    #pragma unroll
    for (int i = 0; i < 4; i++)
        #pragma unroll
        for (int j = 0; j < 4; j++)
            #pragma unroll
            for (int e = 0; e < 4; e++) c[i][j][e] = 0.f;

    auto load_chunk = [&](int ck, int buf) {
        #pragma unroll
        for (int hh = 0; hh < 2; hh++) {
            int u = tid + 256 * hh;          // 0..511
            int row = u >> 2, sg = (u & 3) * 4;
            uint32_t dst = smb + (uint32_t)(buf * GBUF + row * GST + sg) * 4u;
            #pragma unroll
            for (int t = 0; t < 4; t++)
                cp16(dst + t * GTILE * 4, gt[t] + (size_t)row * KW + ck * 16 + sg);
        }
    };

    const int nck = K / 32;
    load_chunk(0, 0); cp_commit();

    for (int ck = 0; ck < nck; ck++) {
        cp_wait<0>();
        __syncthreads();
        if (ck + 1 < nck) { load_chunk(ck + 1, (ck + 1) & 1); cp_commit(); }

        const uint32_t* sAh = su + (ck & 1) * GBUF;
        const uint32_t* sAl = sAh + GTILE;
        const uint32_t* sBh = sAh + 2 * GTILE;
        const uint32_t* sBl = sAh + 3 * GTILE;

        #pragma unroll
        for (int ks = 0; ks < 2; ks++) {
            uint32_t ah[4][4], al[4][4], bh[4][2], bl[4][2];
            #pragma unroll
            for (int i = 0; i < 4; i++) {
                int ab = (wm + 16 * i + g) * GST + ks * 8 + t4;
                ah[i][0] = sAh[ab];            ah[i][1] = sAh[ab + 8 * GST];
                ah[i][2] = sAh[ab + 4];        ah[i][3] = sAh[ab + 8 * GST + 4];
                al[i][0] = sAl[ab];            al[i][1] = sAl[ab + 8 * GST];
                al[i][2] = sAl[ab + 4];        al[i][3] = sAl[ab + 8 * GST + 4];
            }
            #pragma unroll
            for (int j = 0; j < 4; j++) {
                int nb = (wn + 8 * j + g) * GST + ks * 8 + t4;
                bh[j][0] = sBh[nb]; bh[j][1] = sBh[nb + 4];
                bl[j][0] = sBl[nb]; bl[j][1] = sBl[nb + 4];
            }
            #pragma unroll
            for (int i = 0; i < 4; i++)
                #pragma unroll
                for (int j = 0; j < 4; j++) {
                    mma_bf16(c[i][j], ah[i], bh[j]);
                    mma_bf16(c[i][j], ah[i], bl[j]);
                    mma_bf16(c[i][j], al[i], bh[j]);
                }
        }
        __syncthreads();
    }

    // epilogue
    if (mode == 0) {
        #pragma unroll
        for (int j = 0; j < 4; j++) {
            int col = bn + wn + 8 * j + 2 * t4;
            float b0 = bias[col], b1 = bias[col + 1];
            #pragma unroll
            for (int i = 0; i < 4; i++) {
                int row = bm + wm + 16 * i + g;
                *(float2*)&Cf[(size_t)row * N + col] =
                    make_float2(c[i][j][0] + b0, c[i][j][1] + b1);
                *(float2*)&Cf[(size_t)(row + 8) * N + col] =
                    make_float2(c[i][j][2] + b0, c[i][j][3] + b1);
            }
        }
    } else {
        const int NW = N >> 1;
        #pragma unroll
        for (int j = 0; j < 4; j++) {
            int col = bn + wn + 8 * j + 2 * t4;
            int ncol = (col >> 1);
            float b0 = bias[col], b1 = bias[col + 1];
            #pragma unroll
            for (int i = 0; i < 4; i++) {
                int row = bm + wm + 16 * i + g;
                uint32_t hp_, lp_;
                split2(c[i][j][0] + b0, c[i][j][1] + b1, hp_, lp_);
                Ch[(size_t)row * NW + ncol] = hp_;
                Cl[(size_t)row * NW + ncol] = lp_;
                split2(c[i][j][2] + b0, c[i][j][3] + b1, hp_, lp_);
                Ch[(size_t)(row + 8) * NW + ncol] = hp_;
                Cl[(size_t)(row + 8) * NW + ncol] = lp_;
            }
        }
    }
}

// ---------------- V transpose: [token][dpair] -> per (b,h): [d][keypair] ----------------
__global__ void __launch_bounds__(256) vtrans_kernel(
    const uint32_t* __restrict__ Vh, const uint32_t* __restrict__ Vl,
    uint32_t* __restrict__ Vth, uint32_t* __restrict__ Vtl)
{
    __shared__ uint32_t sh[64 * 32], sl[64 * 32];
    const int tid = threadIdx.x;
    const int kb = blockIdx.x, h = blockIdx.y, b = blockIdx.z;
    const size_t tokbase = (size_t)b * SEQ + kb * 64;
    const int hp = h * 32;

    #pragma unroll
    for (int m = 0; m < 8; m++) {
        int idx = tid + 256 * m;        // 0..2047
        int row = idx >> 5, col = idx & 31;
        sh[idx] = Vh[(tokbase + row) * KU + hp + col];
        sl[idx] = Vl[(tokbase + row) * KU + hp + col];
    }
    __syncthreads();

    const size_t obase = ((size_t)(b * NH + h) * DK) * (SEQ / 2) + kb * 32;
    #pragma unroll
    for (int m = 0; m < 8; m++) {
        int idx = tid + 256 * m;
        int d = idx >> 5, kp = idx & 31;
        int sel = (d & 1) * 16;
        uint32_t h0 = (sh[(2 * kp) * 32 + (d >> 1)] >> sel) & 0xffffu;
        uint32_t h1 = (sh[(2 * kp + 1) * 32 + (d >> 1)] >> sel) & 0xffffu;
        uint32_t l0 = (sl[(2 * kp) * 32 + (d >> 1)] >> sel) & 0xffffu;
        uint32_t l1 = (sl[(2 * kp + 1) * 32 + (d >> 1)] >> sel) & 0xffffu;
        Vth[obase + (size_t)d * (SEQ / 2) + kp] = h0 | (h1 << 16);
        Vtl[obase + (size_t)d * (SEQ / 2) + kp] = l0 | (l1 << 16);
    }
}

// ---------------- attention (bf16x3 mma) ----------------
// grid (SEQ/128, NH, BATCH), 256 threads / 8 warps, 16 q-rows per warp.
// smem u32 layout: 2 KV bufs of 4 tiles (Kh,Kl,Vh,Vl; 64x36 each), then Ph, Pl (128x36).
#define AST 36
#define KVT (64 * AST)                 // 2304 u32
#define KVBUF (4 * KVT)                // 9216 u32
#define POFF (2 * KVBUF)               // 18432 u32
#define ATTN_SMEM ((POFF + 2 * 128 * AST) * 4)   // 110592 B

__global__ void __launch_bounds__(256, 1) attn_bf16_kernel(
    const uint32_t* __restrict__ Qh, const uint32_t* __restrict__ Ql,
    const uint32_t* __restrict__ Kh, const uint32_t* __restrict__ Kl,
    const uint32_t* __restrict__ Vth, const uint32_t* __restrict__ Vtl,
    uint32_t* __restrict__ Xh, uint32_t* __restrict__ Xl)
{
    extern __shared__ uint32_t su[];
    const uint32_t smb = smem_u32(su);
    const int tid = threadIdx.x;
    const int wid = tid >> 5, lane = tid & 31;
    const int g = lane >> 2, t4 = lane & 3;
    const int qblk = blockIdx.x, h = blockIdx.y, b = blockIdx.z;
    const int hp = h * 32;
    const size_t tok0 = (size_t)b * SEQ;
    const int q0 = qblk * 128;
    const size_t vbase = ((size_t)(b * NH + h) * DK) * (SEQ / 2);

    uint32_t* Ph = su + POFF;
    uint32_t* Pl = Ph + 128 * AST;

    // preload Q fragments (reused for all K-tiles)
    uint32_t aqh[4][4], aql[4][4];
    {
        const size_t r0 = (tok0 + q0 + wid * 16 + g) * KU + hp;
        const size_t r8 = r0 + 8 * KU;
        #pragma unroll
        for (int ks = 0; ks < 4; ks++) {
            int cc = ks * 8 + t4;
            aqh[ks][0] = Qh[r0 + cc];     aqh[ks][1] = Qh[r8 + cc];
            aqh[ks][2] = Qh[r0 + cc + 4]; aqh[ks][3] = Qh[r8 + cc + 4];
            aql[ks][0] = Ql[r0 + cc];     aql[ks][1] = Ql[r8 + cc];
            aql[ks][2] = Ql[r0 + cc + 4]; aql[ks][3] = Ql[r8 + cc + 4];
        }
    }

    float O[8][4];
    #pragma unroll
    for (int j = 0; j < 8; j++)
        #pragma unroll
        for (int e = 0; e < 4; e++) O[j][e] = 0.f;
    float m0 = -1e30f, m1 = -1e30f, l0 = 0.f, l1 = 0.f;

    auto tile_cp = [&](int kt, int buf) {
        uint32_t bb = smb + (uint32_t)buf * KVBUF * 4u;
        #pragma unroll
        for (int hh = 0; hh < 2; hh++) {
            int u = tid + 256 * hh;         // 0..511
            int row = u >> 3, seg = (u & 7) * 4;
            const size_t ktok = (tok0 + (size_t)kt * 64 + row) * KU + hp + seg;
            cp16(bb + (uint32_t)(row * AST + seg) * 4u, Kh + ktok);
            cp16(bb + (uint32_t)(KVT + row * AST + seg) * 4u, Kl + ktok);
            const size_t vpos = vbase + (size_t)row * (SEQ / 2) + (size_t)kt * 32 + seg;
            cp16(bb + (uint32_t)(2 * KVT + row * AST + seg) * 4u, Vth + vpos);
            cp16(bb + (uint32_t)(3 * KVT + row * AST + seg) * 4u, Vtl + vpos);
        }
    };

    tile_cp(0, 0); cp_commit();

    const int NT = SEQ / 64;   // 32
    for (int kt = 0; kt < NT; kt++) {
        cp_wait<0>();
        __syncthreads();
        if (kt + 1 < NT) { tile_cp(kt + 1, (kt + 1) & 1); cp_commit(); }

        const uint32_t* sKh = su + (kt & 1) * KVBUF;
        const uint32_t* sKl = sKh + KVT;
        const uint32_t* sVh = sKh + 2 * KVT;
        const uint32_t* sVl = sKh + 3 * KVT;

        // ---- S = Q K^T (bf16x3) ----
        float s[8][4];
        #pragma unroll
        for (int j = 0; j < 8; j++)
            #pragma unroll
            for (int e = 0; e < 4; e++) s[j][e] = 0.f;

        #pragma unroll
        for (int ks = 0; ks < 4; ks++) {
            #pragma unroll
            for (int j = 0; j < 8; j++) {
                int nb = (8 * j + g) * AST + ks * 8 + t4;
                uint32_t bh[2] = {sKh[nb], sKh[nb + 4]};
                uint32_t bl[2] = {sKl[nb], sKl[nb + 4]};
                mma_bf16(s[j], aqh[ks], bh);
                mma_bf16(s[j], aqh[ks], bl);
                mma_bf16(s[j], aql[ks], bh);
            }
        }

        // ---- online softmax (rows g and g+8 of this warp's 16) ----
        float mx0 = -1e30f, mx1 = -1e30f;
        #pragma unroll
        for (int j = 0; j < 8; j++) {
            s[j][0] *= 0.125f; s[j][1] *= 0.125f; s[j][2] *= 0.125f; s[j][3] *= 0.125f;
            mx0 = fmaxf(mx0, fmaxf(s[j][0], s[j][1]));
            mx1 = fmaxf(mx1, fmaxf(s[j][2], s[j][3]));
        }
        mx0 = fmaxf(mx0, __shfl_xor_sync(0xffffffffu, mx0, 1));
        mx0 = fmaxf(mx0, __shfl_xor_sync(0xffffffffu, mx0, 2));
        mx1 = fmaxf(mx1, __shfl_xor_sync(0xffffffffu, mx1, 1));
        mx1 = fmaxf(mx1, __shfl_xor_sync(0xffffffffu, mx1, 2));

        float nm0 = fmaxf(m0, mx0), nm1 = fmaxf(m1, mx1);
        float cr0 = __expf(m0 - nm0), cr1 = __expf(m1 - nm1);
        m0 = nm0; m1 = nm1;

        float sum0 = 0.f, sum1 = 0.f;
        #pragma unroll
        for (int j = 0; j < 8; j++) {
            s[j][0] = __expf(s[j][0] - m0);
            s[j][1] = __expf(s[j][1] - m0);
            s[j][2] = __expf(s[j][2] - m1);
            s[j][3] = __expf(s[j][3] - m1);
            sum0 += s[j][0] + s[j][1];
            sum1 += s[j][2] + s[j][3];
        }
        sum0 += __shfl_xor_sync(0xffffffffu, sum0, 1);
        sum0 += __shfl_xor_sync(0xffffffffu, sum0, 2);
        sum1 += __shfl_xor_sync(0xffffffffu, sum1, 1);
        sum1 += __shfl_xor_sync(0xffffffffu, sum1, 2);
        l0 = l0 * cr0 + sum0;
        l1 = l1 * cr1 + sum1;

        #pragma unroll
        for (int j = 0; j < 8; j++) {
            O[j][0] *= cr0; O[j][1] *= cr0; O[j][2] *= cr1; O[j][3] *= cr1;
        }

        // ---- write P (bf16 hi/lo) to smem ----
        {
            int pr = (wid * 16 + g) * AST;
            #pragma unroll
            for (int j = 0; j < 8; j++) {
                uint32_t hp_, lp_;
                split2(s[j][0], s[j][1], hp_, lp_);
                Ph[pr + 4 * j + t4] = hp_;
                Pl[pr + 4 * j + t4] = lp_;
                split2(s[j][2], s[j][3], hp_, lp_);
                Ph[pr + 8 * AST + 4 * j + t4] = hp_;
                Pl[pr + 8 * AST + 4 * j + t4] = lp_;
            }
        }
        __syncthreads();

        // ---- O += P V (bf16x3) ----
        #pragma unroll
        for (int ks = 0; ks < 4; ks++) {
            int ab = (wid * 16 + g) * AST + ks * 8 + t4;
            uint32_t ah[4] = {Ph[ab], Ph[ab + 8 * AST], Ph[ab + 4], Ph[ab + 8 * AST + 4]};
            uint32_t al[4] = {Pl[ab], Pl[ab + 8 * AST], Pl[ab + 4], Pl[ab + 8 * AST + 4]};
            #pragma unroll
            for (int j = 0; j < 8; j++) {
                int nb = (8 * j + g) * AST + ks * 8 + t4;
                uint32_t bh[2] = {sVh[nb], sVh[nb + 4]};
                uint32_t bl[2] = {sVl[nb], sVl[nb + 4]};
                mma_bf16(O[j], ah, bh);
                mma_bf16(O[j], ah, bl);
                mma_bf16(O[j], al, bh);
            }
        }
    }

    // ---- epilogue: normalize, split, store X ----
    {
        float i0 = 1.f / l0, i1 = 1.f / l1;
        const size_t r0 = (tok0 + q0 + wid * 16 + g) * KU + hp;
        const size_t r8 = r0 + 8 * KU;
        #pragma unroll
        for (int j = 0; j < 8; j++) {
            uint32_t hp_, lp_;
            split2(O[j][0] * i0, O[j][1] * i0, hp_, lp_);
            Xh[r0 + 4 * j + t4] = hp_;
            Xl[r0 + 4 * j + t4] = lp_;
            split2(O[j][2] * i1, O[j][3] * i1, hp_, lp_);
            Xh[r8 + 4 * j + t4] = hp_;
            Xl[r8 + 4 * j + t4] = lp_;
        }
    }
}

// ---------------- launch ----------------
extern "C" void kernel_launch(void* const* d_in, const int* in_sizes, int n_in,
                              void* d_out, int out_size)
{
    const float* q  = (const float*)d_in[0];
    const float* k  = (const float*)d_in[1];
    const float* v  = (const float*)d_in[2];
    const float* Wq = (const float*)d_in[3];
    const float* bq = (const float*)d_in[4];
    const float* Wk = (const float*)d_in[5];
    const float* bk = (const float*)d_in[6];
    const float* Wv = (const float*)d_in[7];
    const float* bv = (const float*)d_in[8];
    const float* Wo = (const float*)d_in[9];
    const float* bo = (const float*)d_in[10];
    float* out = (float*)d_out;

    uint32_t *qh, *ql, *kh, *kl, *vh, *vl;
    uint32_t *Wqh, *Wql, *Wkh, *Wkl, *Wvh, *Wvl, *Woh, *Wol;
    uint32_t *Qh, *Ql, *Kh, *Kl, *Vh, *Vl, *Vth, *Vtl, *Xh, *Xl;
    cudaGetSymbolAddress((void**)&qh, g_qh);   cudaGetSymbolAddress((void**)&ql, g_ql);
    cudaGetSymbolAddress((void**)&kh, g_kh);   cudaGetSymbolAddress((void**)&kl, g_kl);
    cudaGetSymbolAddress((void**)&vh, g_vh);   cudaGetSymbolAddress((void**)&vl, g_vl);
    cudaGetSymbolAddress((void**)&Wqh, g_Wqh); cudaGetSymbolAddress((void**)&Wql, g_Wql);
    cudaGetSymbolAddress((void**)&Wkh, g_Wkh); cudaGetSymbolAddress((void**)&Wkl, g_Wkl);
    cudaGetSymbolAddress((void**)&Wvh, g_Wvh); cudaGetSymbolAddress((void**)&Wvl, g_Wvl);
    cudaGetSymbolAddress((void**)&Woh, g_Woh); cudaGetSymbolAddress((void**)&Wol, g_Wol);
    cudaGetSymbolAddress((void**)&Qh, g_Qh);   cudaGetSymbolAddress((void**)&Ql, g_Ql);
    cudaGetSymbolAddress((void**)&Kh, g_Kh);   cudaGetSymbolAddress((void**)&Kl, g_Kl);
    cudaGetSymbolAddress((void**)&Vh, g_Vh);   cudaGetSymbolAddress((void**)&Vl, g_Vl);
    cudaGetSymbolAddress((void**)&Vth, g_Vth); cudaGetSymbolAddress((void**)&Vtl, g_Vtl);
    cudaGetSymbolAddress((void**)&Xh, g_Xh);   cudaGetSymbolAddress((void**)&Xl, g_Xl);

    cudaFuncSetAttribute(gemm_bf16x3_kernel,
                         cudaFuncAttributeMaxDynamicSharedMemorySize, GEMM_SMEM);
    cudaFuncSetAttribute(attn_bf16_kernel,
                         cudaFuncAttributeMaxDynamicSharedMemorySize, ATTN_SMEM);

    const int nAct4 = MT * D_MODEL / 4;       // 1M float4
    const int nW4   = D_MODEL * D_MODEL / 4;  // 256K float4

    cvt_kernel<<<1024, 256>>>(q, qh, ql, nAct4);
    cvt_kernel<<<1024, 256>>>(k, kh, kl, nAct4);
    cvt_kernel<<<1024, 256>>>(v, vh, vl, nAct4);
    cvt_kernel<<<512, 256>>>(Wq, Wqh, Wql, nW4);
    cvt_kernel<<<512, 256>>>(Wk, Wkh, Wkl, nW4);
    cvt_kernel<<<512, 256>>>(Wv, Wvh, Wvl, nW4);
    cvt_kernel<<<512, 256>>>(Wo, Woh, Wol, nW4);

    dim3 ggrid(D_MODEL / 128, MT / 128);      // (8, 32)
    gemm_bf16x3_kernel<<<ggrid, 256, GEMM_SMEM>>>(qh, ql, Wqh, Wql, bq,
                                                  nullptr, Qh, Ql, MT, D_MODEL, D_MODEL, 1);
    gemm_bf16x3_kernel<<<ggrid, 256, GEMM_SMEM>>>(kh, kl, Wkh, Wkl, bk,
                                                  nullptr, Kh, Kl, MT, D_MODEL, D_MODEL, 1);
    gemm_bf16x3_kernel<<<ggrid, 256, GEMM_SMEM>>>(vh, vl, Wvh, Wvl, bv,
                                                  nullptr, Vh, Vl, MT, D_MODEL, D_MODEL, 1);

    dim3 tgrid(SEQ / 64, NH, BATCH);          // (32, 16, 2)
    vtrans_kernel<<<tgrid, 256>>>(Vh, Vl, Vth, Vtl);

    dim3 agrid(SEQ / 128, NH, BATCH);         // (16, 16, 2)
    attn_bf16_kernel<<<agrid, 256, ATTN_SMEM>>>(Qh, Ql, Kh, Kl, Vth, Vtl, Xh, Xl);

    gemm_bf16x3_kernel<<<ggrid, 256, GEMM_SMEM>>>(Xh, Xl, Woh, Wol, bo,
                                                  out, nullptr, nullptr, MT, D_MODEL, D_MODEL, 0);
}

// round 5
// speedup vs baseline: 4.5092x; 1.0308x over previous
#include <cuda_runtime.h>
#include <cuda_bf16.h>
#include <math.h>
#include <cstdint>

#define D_MODEL 1024
#define NH 16
#define DK 64
#define BATCH 2
#define SEQ 2048
#define MT (BATCH * SEQ)        // 4096
#define KU (D_MODEL / 2)        // 512 u32 (bf16 pairs) per row

// ---------------- scratch (device globals) ----------------
__device__ uint32_t g_qh[MT * KU],  g_ql[MT * KU];
__device__ uint32_t g_kh[MT * KU],  g_kl[MT * KU];
__device__ uint32_t g_vh[MT * KU],  g_vl[MT * KU];
__device__ uint32_t g_Wqh[D_MODEL * KU], g_Wql[D_MODEL * KU];
__device__ uint32_t g_Wkh[D_MODEL * KU], g_Wkl[D_MODEL * KU];
__device__ uint32_t g_Wvh[D_MODEL * KU], g_Wvl[D_MODEL * KU];
__device__ uint32_t g_Woh[D_MODEL * KU], g_Wol[D_MODEL * KU];
__device__ uint32_t g_Qh[MT * KU], g_Ql[MT * KU];
__device__ uint32_t g_Kh[MT * KU], g_Kl[MT * KU];
__device__ uint32_t g_Vh[MT * KU], g_Vl[MT * KU];
__device__ uint32_t g_Vth[BATCH * NH * DK * (SEQ / 2)], g_Vtl[BATCH * NH * DK * (SEQ / 2)];
__device__ uint32_t g_Xh[MT * KU], g_Xl[MT * KU];

// ---------------- helpers ----------------
__device__ __forceinline__ uint32_t smem_u32(const void* p) {
    uint32_t a;
    asm("{ .reg .u64 t; cvta.to.shared.u64 t, %1; cvt.u32.u64 %0, t; }" : "=r"(a) : "l"(p));
    return a;
}
__device__ __forceinline__ void cp16(uint32_t s, const void* g) {
    asm volatile("cp.async.cg.shared.global [%0], [%1], 16;" :: "r"(s), "l"(g));
}
__device__ __forceinline__ void cp_commit() {
    asm volatile("cp.async.commit_group;" ::: "memory");
}
template <int N>
__device__ __forceinline__ void cp_wait() {
    asm volatile("cp.async.wait_group %0;" :: "n"(N) : "memory");
}
__device__ __forceinline__ void ldsm4(uint32_t& r0, uint32_t& r1, uint32_t& r2, uint32_t& r3,
                                      uint32_t addr) {
    asm volatile("ldmatrix.sync.aligned.m8n8.x4.shared.b16 {%0,%1,%2,%3}, [%4];"
                 : "=r"(r0), "=r"(r1), "=r"(r2), "=r"(r3) : "r"(addr));
}

// bf16 mma: D(16x8,f32) += A(16x16,bf16) * B(16x8,bf16)
__device__ __forceinline__ void mma_bf16(float c[4], const uint32_t a[4], const uint32_t b[2]) {
    asm volatile(
        "mma.sync.aligned.m16n8k16.row.col.f32.bf16.bf16.f32 "
        "{%0,%1,%2,%3}, {%4,%5,%6,%7}, {%8,%9}, {%0,%1,%2,%3};"
        : "+f"(c[0]), "+f"(c[1]), "+f"(c[2]), "+f"(c[3])
        : "r"(a[0]), "r"(a[1]), "r"(a[2]), "r"(a[3]), "r"(b[0]), "r"(b[1]));
}

// split two fp32 into packed bf16 hi-pair and lo-pair (v0 -> low 16 bits)
__device__ __forceinline__ void split2(float v0, float v1, uint32_t& hp, uint32_t& lp) {
    __nv_bfloat162 hh, ll;
    hh.x = __float2bfloat16_rn(v0);
    hh.y = __float2bfloat16_rn(v1);
    ll.x = __float2bfloat16_rn(v0 - __bfloat162float(hh.x));
    ll.y = __float2bfloat16_rn(v1 - __bfloat162float(hh.y));
    hp = *reinterpret_cast<uint32_t*>(&hh);
    lp = *reinterpret_cast<uint32_t*>(&ll);
}

// ---------------- fused fp32 -> bf16 hi/lo conversion (ONE launch) ----------------
__global__ void __launch_bounds__(256) cvt_all_kernel(
    const float* __restrict__ q, const float* __restrict__ k, const float* __restrict__ v,
    const float* __restrict__ Wq, const float* __restrict__ Wk,
    const float* __restrict__ Wv, const float* __restrict__ Wo,
    uint32_t* qh, uint32_t* ql, uint32_t* kh, uint32_t* kl, uint32_t* vh, uint32_t* vl,
    uint32_t* Wqh, uint32_t* Wql, uint32_t* Wkh, uint32_t* Wkl,
    uint32_t* Wvh, uint32_t* Wvl, uint32_t* Woh, uint32_t* Wol)
{
    const int z = blockIdx.y;
    const float* in;
    uint32_t *h, *l;
    int n4;
    const int nAct4 = MT * D_MODEL / 4, nW4 = D_MODEL * D_MODEL / 4;
    switch (z) {
        case 0: in = q;  h = qh;  l = ql;  n4 = nAct4; break;
        case 1: in = k;  h = kh;  l = kl;  n4 = nAct4; break;
        case 2: in = v;  h = vh;  l = vl;  n4 = nAct4; break;
        case 3: in = Wq; h = Wqh; l = Wql; n4 = nW4;   break;
        case 4: in = Wk; h = Wkh; l = Wkl; n4 = nW4;   break;
        case 5: in = Wv; h = Wvh; l = Wvl; n4 = nW4;   break;
        default: in = Wo; h = Woh; l = Wol; n4 = nW4;  break;
    }
    int i = blockIdx.x * blockDim.x + threadIdx.x;
    const int stride = gridDim.x * blockDim.x;
    for (; i < n4; i += stride) {
        float4 x = ((const float4*)in)[i];
        uint32_t h0, l0, h1, l1;
        split2(x.x, x.y, h0, l0);
        split2(x.z, x.w, h1, l1);
        ((uint2*)h)[i] = make_uint2(h0, h1);
        ((uint2*)l)[i] = make_uint2(l0, l1);
    }
}

// ---------------- bf16x3 GEMM: C = A*B^T + bias ----------------
// CTA 128x128, kchunk 32, 8 warps (warp tile 64x32). ldmatrix fragment loads.
#define GST 20                     // smem row stride (u32)
#define GTILE (128 * GST)          // 2560 u32 per tile
#define GBUF (4 * GTILE)           // Ah, Al, Bh, Bl
#define GEMM_SMEM (2 * GBUF * 4)   // 81920 B

__global__ void __launch_bounds__(256, 1) gemm_bf16x3_kernel(
    const uint32_t* __restrict__ Ah, const uint32_t* __restrict__ Al,
    const uint32_t* __restrict__ Bh, const uint32_t* __restrict__ Bl,
    const float* __restrict__ bias,
    float* __restrict__ Cf, uint32_t* __restrict__ Ch, uint32_t* __restrict__ Cl,
    int M, int N, int K, int mode)
{
    extern __shared__ uint32_t su[];
    const uint32_t smb = smem_u32(su);
    const int tid = threadIdx.x;
    const int wid = tid >> 5, lane = tid & 31;
    const int g = lane >> 2, t4 = lane & 3;
    const int qm = lane >> 3, rm = lane & 7;
    const int bm = blockIdx.y * 128, bn = blockIdx.x * 128;
    const int wm = (wid >> 2) * 64, wn = (wid & 3) * 32;
    const int KW = K >> 1;

    const uint32_t* gt[4];
    gt[0] = Ah + (size_t)bm * KW;
    gt[1] = Al + (size_t)bm * KW;
    gt[2] = Bh + (size_t)bn * KW;
    gt[3] = Bl + (size_t)bn * KW;

    float c[4][4][4];
    #pragma unroll
    for (int i = 0; i < 4; i++)
        #pragma unroll
        for (int j = 0; j < 4; j++)
            #pragma unroll
            for (int e = 0; e < 4; e++) c[i][j][e] = 0.f;

    auto load_chunk = [&](int ck, int buf) {
        #pragma unroll
        for (int hh = 0; hh < 2; hh++) {
            int u = tid + 256 * hh;          // 0..511
            int row = u >> 2, sg = (u & 3) * 4;
            uint32_t dst = smb + (uint32_t)(buf * GBUF + row * GST + sg) * 4u;
            #pragma unroll
            for (int t = 0; t < 4; t++)
                cp16(dst + t * GTILE * 4, gt[t] + (size_t)row * KW + ck * 16 + sg);
        }
    };

    // ldmatrix lane bases (u32 units within a tile)
    const int aLane = (wm + (qm & 1) * 8 + rm) * GST + (qm >> 1) * 4;
    const int bLane = (wn + (qm >> 1) * 8 + rm) * GST + (qm & 1) * 4;

    const int nck = K / 32;
    load_chunk(0, 0); cp_commit();

    for (int ck = 0; ck < nck; ck++) {
        cp_wait<0>();
        __syncthreads();
        if (ck + 1 < nck) { load_chunk(ck + 1, (ck + 1) & 1); cp_commit(); }

        const uint32_t bufAddr = smb + (uint32_t)((ck & 1) * GBUF) * 4u;
        const uint32_t sAhA = bufAddr;
        const uint32_t sAlA = bufAddr + GTILE * 4u;
        const uint32_t sBhA = bufAddr + 2u * GTILE * 4u;
        const uint32_t sBlA = bufAddr + 3u * GTILE * 4u;

        #pragma unroll
        for (int ks = 0; ks < 2; ks++) {
            uint32_t ah[4][4], al[4][4], bh[4][2], bl[4][2];
            #pragma unroll
            for (int i = 0; i < 4; i++) {
                uint32_t off = (uint32_t)(aLane + i * 16 * GST + ks * 8) * 4u;
                ldsm4(ah[i][0], ah[i][1], ah[i][2], ah[i][3], sAhA + off);
                ldsm4(al[i][0], al[i][1], al[i][2], al[i][3], sAlA + off);
            }
            #pragma unroll
            for (int jp = 0; jp < 2; jp++) {
                uint32_t off = (uint32_t)(bLane + jp * 16 * GST + ks * 8) * 4u;
                ldsm4(bh[2 * jp][0], bh[2 * jp][1], bh[2 * jp + 1][0], bh[2 * jp + 1][1],
                      sBhA + off);
                ldsm4(bl[2 * jp][0], bl[2 * jp][1], bl[2 * jp + 1][0], bl[2 * jp + 1][1],
                      sBlA + off);
            }
            #pragma unroll
            for (int i = 0; i < 4; i++)
                #pragma unroll
                for (int j = 0; j < 4; j++) {
                    mma_bf16(c[i][j], ah[i], bh[j]);
                    mma_bf16(c[i][j], ah[i], bl[j]);
                    mma_bf16(c[i][j], al[i], bh[j]);
                }
        }
        __syncthreads();
    }

    // epilogue
    if (mode == 0) {
        #pragma unroll
        for (int j = 0; j < 4; j++) {
            int col = bn + wn + 8 * j + 2 * t4;
            float b0 = bias[col], b1 = bias[col + 1];
            #pragma unroll
            for (int i = 0; i < 4; i++) {
                int row = bm + wm + 16 * i + g;
                *(float2*)&Cf[(size_t)row * N + col] =
                    make_float2(c[i][j][0] + b0, c[i][j][1] + b1);
                *(float2*)&Cf[(size_t)(row + 8) * N + col] =
                    make_float2(c[i][j][2] + b0, c[i][j][3] + b1);
            }
        }
    } else {
        const int NW = N >> 1;
        #pragma unroll
        for (int j = 0; j < 4; j++) {
            int col = bn + wn + 8 * j + 2 * t4;
            int ncol = (col >> 1);
            float b0 = bias[col], b1 = bias[col + 1];
            #pragma unroll
            for (int i = 0; i < 4; i++) {
                int row = bm + wm + 16 * i + g;
                uint32_t hp_, lp_;
                split2(c[i][j][0] + b0, c[i][j][1] + b1, hp_, lp_);
                Ch[(size_t)row * NW + ncol] = hp_;
                Cl[(size_t)row * NW + ncol] = lp_;
                split2(c[i][j][2] + b0, c[i][j][3] + b1, hp_, lp_);
                Ch[(size_t)(row + 8) * NW + ncol] = hp_;
                Cl[(size_t)(row + 8) * NW + ncol] = lp_;
            }
        }
    }
}

// ---------------- V transpose: [token][dpair] -> per (b,h): [d][keypair] ----------------
__global__ void __launch_bounds__(256) vtrans_kernel(
    const uint32_t* __restrict__ Vh, const uint32_t* __restrict__ Vl,
    uint32_t* __restrict__ Vth, uint32_t* __restrict__ Vtl)
{
    __shared__ uint32_t sh[64 * 32], sl[64 * 32];
    const int tid = threadIdx.x;
    const int kb = blockIdx.x, h = blockIdx.y, b = blockIdx.z;
    const size_t tokbase = (size_t)b * SEQ + kb * 64;
    const int hp = h * 32;

    #pragma unroll
    for (int m = 0; m < 8; m++) {
        int idx = tid + 256 * m;        // 0..2047
        int row = idx >> 5, col = idx & 31;
        sh[idx] = Vh[(tokbase + row) * KU + hp + col];
        sl[idx] = Vl[(tokbase + row) * KU + hp + col];
    }
    __syncthreads();

    const size_t obase = ((size_t)(b * NH + h) * DK) * (SEQ / 2) + kb * 32;
    #pragma unroll
    for (int m = 0; m < 8; m++) {
        int idx = tid + 256 * m;
        int d = idx >> 5, kp = idx & 31;
        int sel = (d & 1) * 16;
        uint32_t h0 = (sh[(2 * kp) * 32 + (d >> 1)] >> sel) & 0xffffu;
        uint32_t h1 = (sh[(2 * kp + 1) * 32 + (d >> 1)] >> sel) & 0xffffu;
        uint32_t l0 = (sl[(2 * kp) * 32 + (d >> 1)] >> sel) & 0xffffu;
        uint32_t l1 = (sl[(2 * kp + 1) * 32 + (d >> 1)] >> sel) & 0xffffu;
        Vth[obase + (size_t)d * (SEQ / 2) + kp] = h0 | (h1 << 16);
        Vtl[obase + (size_t)d * (SEQ / 2) + kp] = l0 | (l1 << 16);
    }
}

// ---------------- attention (bf16x3 mma + ldmatrix) ----------------
#define AST 36
#define KVT (64 * AST)                 // 2304 u32
#define KVBUF (4 * KVT)                // 9216 u32
#define POFF (2 * KVBUF)               // 18432 u32
#define ATTN_SMEM ((POFF + 2 * 128 * AST) * 4)   // 110592 B
#define SM_C 0.18033688f               // 0.125 * log2(e)

__global__ void __launch_bounds__(256, 1) attn_bf16_kernel(
    const uint32_t* __restrict__ Qh, const uint32_t* __restrict__ Ql,
    const uint32_t* __restrict__ Kh, const uint32_t* __restrict__ Kl,
    const uint32_t* __restrict__ Vth, const uint32_t* __restrict__ Vtl,
    uint32_t* __restrict__ Xh, uint32_t* __restrict__ Xl)
{
    extern __shared__ uint32_t su[];
    const uint32_t smb = smem_u32(su);
    const int tid = threadIdx.x;
    const int wid = tid >> 5, lane = tid & 31;
    const int g = lane >> 2, t4 = lane & 3;
    const int qm = lane >> 3, rm = lane & 7;
    const int qblk = blockIdx.x, h = blockIdx.y, b = blockIdx.z;
    const int hp = h * 32;
    const size_t tok0 = (size_t)b * SEQ;
    const int q0 = qblk * 128;
    const size_t vbase = ((size_t)(b * NH + h) * DK) * (SEQ / 2);

    const uint32_t PhA = smb + (uint32_t)POFF * 4u;
    const uint32_t PlA = PhA + 128u * AST * 4u;
    uint32_t* Ph = su + POFF;
    uint32_t* Pl = Ph + 128 * AST;

    // preload Q fragments (reused for all K-tiles)
    uint32_t aqh[4][4], aql[4][4];
    {
        const size_t r0 = (tok0 + q0 + wid * 16 + g) * KU + hp;
        const size_t r8 = r0 + 8 * KU;
        #pragma unroll
        for (int ks = 0; ks < 4; ks++) {
            int cc = ks * 8 + t4;
            aqh[ks][0] = Qh[r0 + cc];     aqh[ks][1] = Qh[r8 + cc];
            aqh[ks][2] = Qh[r0 + cc + 4]; aqh[ks][3] = Qh[r8 + cc + 4];
            aql[ks][0] = Ql[r0 + cc];     aql[ks][1] = Ql[r8 + cc];
            aql[ks][2] = Ql[r0 + cc + 4]; aql[ks][3] = Ql[r8 + cc + 4];
        }
    }

    float O[8][4];
    #pragma unroll
    for (int j = 0; j < 8; j++)
        #pragma unroll
        for (int e = 0; e < 4; e++) O[j][e] = 0.f;
    float m0 = -1e30f, m1 = -1e30f, l0 = 0.f, l1 = 0.f;

    auto tile_cp = [&](int kt, int buf) {
        uint32_t bb = smb + (uint32_t)buf * KVBUF * 4u;
        #pragma unroll
        for (int hh = 0; hh < 2; hh++) {
            int u = tid + 256 * hh;         // 0..511
            int row = u >> 3, seg = (u & 7) * 4;
            const size_t ktok = (tok0 + (size_t)kt * 64 + row) * KU + hp + seg;
            cp16(bb + (uint32_t)(row * AST + seg) * 4u, Kh + ktok);
            cp16(bb + (uint32_t)(KVT + row * AST + seg) * 4u, Kl + ktok);
            const size_t vpos = vbase + (size_t)row * (SEQ / 2) + (size_t)kt * 32 + seg;
            cp16(bb + (uint32_t)(2 * KVT + row * AST + seg) * 4u, Vth + vpos);
            cp16(bb + (uint32_t)(3 * KVT + row * AST + seg) * 4u, Vtl + vpos);
        }
    };

    // ldmatrix lane bases (u32 units)
    const int kvLane = ((qm >> 1) * 8 + rm) * AST + (qm & 1) * 4;   // B frags (K and Vt)
    const int pLane  = (wid * 16 + (qm & 1) * 8 + rm) * AST + (qm >> 1) * 4;  // P A-frags

    tile_cp(0, 0); cp_commit();

    const int NT = SEQ / 64;   // 32
    for (int kt = 0; kt < NT; kt++) {
        cp_wait<0>();
        __syncthreads();
        if (kt + 1 < NT) { tile_cp(kt + 1, (kt + 1) & 1); cp_commit(); }

        const uint32_t bufA = smb + (uint32_t)((kt & 1) * KVBUF) * 4u;
        const uint32_t sKhA = bufA;
        const uint32_t sKlA = bufA + KVT * 4u;
        const uint32_t sVhA = bufA + 2u * KVT * 4u;
        const uint32_t sVlA = bufA + 3u * KVT * 4u;

        // ---- S = Q K^T (bf16x3) ----
        float s[8][4];
        #pragma unroll
        for (int j = 0; j < 8; j++)
            #pragma unroll
            for (int e = 0; e < 4; e++) s[j][e] = 0.f;

        #pragma unroll
        for (int ks = 0; ks < 4; ks++) {
            uint32_t bh[8][2], bl[8][2];
            #pragma unroll
            for (int jp = 0; jp < 4; jp++) {
                uint32_t off = (uint32_t)(kvLane + jp * 16 * AST + ks * 8) * 4u;
                ldsm4(bh[2 * jp][0], bh[2 * jp][1], bh[2 * jp + 1][0], bh[2 * jp + 1][1],
                      sKhA + off);
                ldsm4(bl[2 * jp][0], bl[2 * jp][1], bl[2 * jp + 1][0], bl[2 * jp + 1][1],
                      sKlA + off);
            }
            #pragma unroll
            for (int j = 0; j < 8; j++) {
                mma_bf16(s[j], aqh[ks], bh[j]);
                mma_bf16(s[j], aqh[ks], bl[j]);
                mma_bf16(s[j], aql[ks], bh[j]);
            }
        }

        // ---- online softmax in exp2 domain (raw scores; p = 2^((s-m)*SM_C)) ----
        float mx0 = -1e30f, mx1 = -1e30f;
        #pragma unroll
        for (int j = 0; j < 8; j++) {
            mx0 = fmaxf(mx0, fmaxf(s[j][0], s[j][1]));
            mx1 = fmaxf(mx1, fmaxf(s[j][2], s[j][3]));
        }
        mx0 = fmaxf(mx0, __shfl_xor_sync(0xffffffffu, mx0, 1));
        mx0 = fmaxf(mx0, __shfl_xor_sync(0xffffffffu, mx0, 2));
        mx1 = fmaxf(mx1, __shfl_xor_sync(0xffffffffu, mx1, 1));
        mx1 = fmaxf(mx1, __shfl_xor_sync(0xffffffffu, mx1, 2));

        float nm0 = fmaxf(m0, mx0), nm1 = fmaxf(m1, mx1);
        float cr0 = exp2f((m0 - nm0) * SM_C), cr1 = exp2f((m1 - nm1) * SM_C);
        m0 = nm0; m1 = nm1;

        float sum0 = 0.f, sum1 = 0.f;
        #pragma unroll
        for (int j = 0; j < 8; j++) {
            s[j][0] = exp2f((s[j][0] - m0) * SM_C);
            s[j][1] = exp2f((s[j][1] - m0) * SM_C);
            s[j][2] = exp2f((s[j][2] - m1) * SM_C);
            s[j][3] = exp2f((s[j][3] - m1) * SM_C);
            sum0 += s[j][0] + s[j][1];
            sum1 += s[j][2] + s[j][3];
        }
        sum0 += __shfl_xor_sync(0xffffffffu, sum0, 1);
        sum0 += __shfl_xor_sync(0xffffffffu, sum0, 2);
        sum1 += __shfl_xor_sync(0xffffffffu, sum1, 1);
        sum1 += __shfl_xor_sync(0xffffffffu, sum1, 2);
        l0 = l0 * cr0 + sum0;
        l1 = l1 * cr1 + sum1;

        #pragma unroll
        for (int j = 0; j < 8; j++) {
            O[j][0] *= cr0; O[j][1] *= cr0; O[j][2] *= cr1; O[j][3] *= cr1;
        }

        // ---- write P (bf16 hi/lo) to smem ----
        {
            int pr = (wid * 16 + g) * AST;
            #pragma unroll
            for (int j = 0; j < 8; j++) {
                uint32_t hp_, lp_;
                split2(s[j][0], s[j][1], hp_, lp_);
                Ph[pr + 4 * j + t4] = hp_;
                Pl[pr + 4 * j + t4] = lp_;
                split2(s[j][2], s[j][3], hp_, lp_);
                Ph[pr + 8 * AST + 4 * j + t4] = hp_;
                Pl[pr + 8 * AST + 4 * j + t4] = lp_;
            }
        }
        __syncthreads();

        // ---- O += P V (bf16x3) ----
        #pragma unroll
        for (int ks = 0; ks < 4; ks++) {
            uint32_t poff = (uint32_t)(pLane + ks * 8) * 4u;
            uint32_t ah[4], al[4];
            ldsm4(ah[0], ah[1], ah[2], ah[3], PhA + poff);
            ldsm4(al[0], al[1], al[2], al[3], PlA + poff);
            uint32_t bh[8][2], bl[8][2];
            #pragma unroll
            for (int jp = 0; jp < 4; jp++) {
                uint32_t off = (uint32_t)(kvLane + jp * 16 * AST + ks * 8) * 4u;
                ldsm4(bh[2 * jp][0], bh[2 * jp][1], bh[2 * jp + 1][0], bh[2 * jp + 1][1],
                      sVhA + off);
                ldsm4(bl[2 * jp][0], bl[2 * jp][1], bl[2 * jp + 1][0], bl[2 * jp + 1][1],
                      sVlA + off);
            }
            #pragma unroll
            for (int j = 0; j < 8; j++) {
                mma_bf16(O[j], ah, bh[j]);
                mma_bf16(O[j], ah, bl[j]);
                mma_bf16(O[j], al, bh[j]);
            }
        }
    }

    // ---- epilogue: normalize, split, store X ----
    {
        float i0 = 1.f / l0, i1 = 1.f / l1;
        const size_t r0 = (tok0 + q0 + wid * 16 + g) * KU + hp;
        const size_t r8 = r0 + 8 * KU;
        #pragma unroll
        for (int j = 0; j < 8; j++) {
            uint32_t hp_, lp_;
            split2(O[j][0] * i0, O[j][1] * i0, hp_, lp_);
            Xh[r0 + 4 * j + t4] = hp_;
            Xl[r0 + 4 * j + t4] = lp_;
            split2(O[j][2] * i1, O[j][3] * i1, hp_, lp_);
            Xh[r8 + 4 * j + t4] = hp_;
            Xl[r8 + 4 * j + t4] = lp_;
        }
    }
}

// ---------------- launch ----------------
extern "C" void kernel_launch(void* const* d_in, const int* in_sizes, int n_in,
                              void* d_out, int out_size)
{
    const float* q  = (const float*)d_in[0];
    const float* k  = (const float*)d_in[1];
    const float* v  = (const float*)d_in[2];
    const float* Wq = (const float*)d_in[3];
    const float* bq = (const float*)d_in[4];
    const float* Wk = (const float*)d_in[5];
    const float* bk = (const float*)d_in[6];
    const float* Wv = (const float*)d_in[7];
    const float* bv = (const float*)d_in[8];
    const float* Wo = (const float*)d_in[9];
    const float* bo = (const float*)d_in[10];
    float* out = (float*)d_out;

    uint32_t *qh, *ql, *kh, *kl, *vh, *vl;
    uint32_t *Wqh, *Wql, *Wkh, *Wkl, *Wvh, *Wvl, *Woh, *Wol;
    uint32_t *Qh, *Ql, *Kh, *Kl, *Vh, *Vl, *Vth, *Vtl, *Xh, *Xl;
    cudaGetSymbolAddress((void**)&qh, g_qh);   cudaGetSymbolAddress((void**)&ql, g_ql);
    cudaGetSymbolAddress((void**)&kh, g_kh);   cudaGetSymbolAddress((void**)&kl, g_kl);
    cudaGetSymbolAddress((void**)&vh, g_vh);   cudaGetSymbolAddress((void**)&vl, g_vl);
    cudaGetSymbolAddress((void**)&Wqh, g_Wqh); cudaGetSymbolAddress((void**)&Wql, g_Wql);
    cudaGetSymbolAddress((void**)&Wkh, g_Wkh); cudaGetSymbolAddress((void**)&Wkl, g_Wkl);
    cudaGetSymbolAddress((void**)&Wvh, g_Wvh); cudaGetSymbolAddress((void**)&Wvl, g_Wvl);
    cudaGetSymbolAddress((void**)&Woh, g_Woh); cudaGetSymbolAddress((void**)&Wol, g_Wol);
    cudaGetSymbolAddress((void**)&Qh, g_Qh);   cudaGetSymbolAddress((void**)&Ql, g_Ql);
    cudaGetSymbolAddress((void**)&Kh, g_Kh);   cudaGetSymbolAddress((void**)&Kl, g_Kl);
    cudaGetSymbolAddress((void**)&Vh, g_Vh);   cudaGetSymbolAddress((void**)&Vl, g_Vl);
    cudaGetSymbolAddress((void**)&Vth, g_Vth); cudaGetSymbolAddress((void**)&Vtl, g_Vtl);
    cudaGetSymbolAddress((void**)&Xh, g_Xh);   cudaGetSymbolAddress((void**)&Xl, g_Xl);

    cudaFuncSetAttribute(gemm_bf16x3_kernel,
                         cudaFuncAttributeMaxDynamicSharedMemorySize, GEMM_SMEM);
    cudaFuncSetAttribute(attn_bf16_kernel,
                         cudaFuncAttributeMaxDynamicSharedMemorySize, ATTN_SMEM);

    // launch 1: fused conversions
    cvt_all_kernel<<<dim3(256, 7), 256>>>(q, k, v, Wq, Wk, Wv, Wo,
                                          qh, ql, kh, kl, vh, vl,
                                          Wqh, Wql, Wkh, Wkl, Wvh, Wvl, Woh, Wol);

    // launches 2-4: projections
    dim3 ggrid(D_MODEL / 128, MT / 128);      // (8, 32)
    gemm_bf16x3_kernel<<<ggrid, 256, GEMM_SMEM>>>(qh, ql, Wqh, Wql, bq,
                                                  nullptr, Qh, Ql, MT, D_MODEL, D_MODEL, 1);
    gemm_bf16x3_kernel<<<ggrid, 256, GEMM_SMEM>>>(kh, kl, Wkh, Wkl, bk,
                                                  nullptr, Kh, Kl, MT, D_MODEL, D_MODEL, 1);
    gemm_bf16x3_kernel<<<ggrid, 256, GEMM_SMEM>>>(vh, vl, Wvh, Wvl, bv,
                                                  nullptr, Vh, Vl, MT, D_MODEL, D_MODEL, 1);

    // launch 5: V transpose
    dim3 tgrid(SEQ / 64, NH, BATCH);          // (32, 16, 2)
    vtrans_kernel<<<tgrid, 256>>>(Vh, Vl, Vth, Vtl);

    // launch 6: attention (ncu -s 5 -c 1 profiles this one)
    dim3 agrid(SEQ / 128, NH, BATCH);         // (16, 16, 2)
    attn_bf16_kernel<<<agrid, 256, ATTN_SMEM>>>(Qh, Ql, Kh, Kl, Vth, Vtl, Xh, Xl);

    // launch 7: output projection
    gemm_bf16x3_kernel<<<ggrid, 256, GEMM_SMEM>>>(Xh, Xl, Woh, Wol, bo,
                                                  out, nullptr, nullptr, MT, D_MODEL, D_MODEL, 0);
}

// round 6
// speedup vs baseline: 4.8456x; 1.0746x over previous
#include <cuda_runtime.h>
#include <cuda_bf16.h>
#include <math.h>
#include <cstdint>

#define D_MODEL 1024
#define NH 16
#define DK 64
#define BATCH 2
#define SEQ 2048
#define MT (BATCH * SEQ)        // 4096
#define KU (D_MODEL / 2)        // 512 u32 (bf16 pairs) per row

// ---------------- scratch (device globals) ----------------
__device__ uint32_t g_qh[MT * KU],  g_ql[MT * KU];
__device__ uint32_t g_kh[MT * KU],  g_kl[MT * KU];
__device__ uint32_t g_vh[MT * KU],  g_vl[MT * KU];
__device__ uint32_t g_Wqh[D_MODEL * KU], g_Wql[D_MODEL * KU];
__device__ uint32_t g_Wkh[D_MODEL * KU], g_Wkl[D_MODEL * KU];
__device__ uint32_t g_Wvh[D_MODEL * KU], g_Wvl[D_MODEL * KU];
__device__ uint32_t g_Woh[D_MODEL * KU], g_Wol[D_MODEL * KU];
__device__ uint32_t g_Qh[MT * KU], g_Ql[MT * KU];
__device__ uint32_t g_Kh[MT * KU], g_Kl[MT * KU];
__device__ uint32_t g_Vh[MT * KU], g_Vl[MT * KU];
__device__ uint32_t g_Vth[BATCH * NH * DK * (SEQ / 2)], g_Vtl[BATCH * NH * DK * (SEQ / 2)];
__device__ uint32_t g_Xh[MT * KU], g_Xl[MT * KU];

// ---------------- helpers ----------------
__device__ __forceinline__ uint32_t smem_u32(const void* p) {
    uint32_t a;
    asm("{ .reg .u64 t; cvta.to.shared.u64 t, %1; cvt.u32.u64 %0, t; }" : "=r"(a) : "l"(p));
    return a;
}
__device__ __forceinline__ void cp16(uint32_t s, const void* g) {
    asm volatile("cp.async.cg.shared.global [%0], [%1], 16;" :: "r"(s), "l"(g));
}
__device__ __forceinline__ void cp_commit() {
    asm volatile("cp.async.commit_group;" ::: "memory");
}
template <int N>
__device__ __forceinline__ void cp_wait() {
    asm volatile("cp.async.wait_group %0;" :: "n"(N) : "memory");
}
__device__ __forceinline__ void ldsm4(uint32_t& r0, uint32_t& r1, uint32_t& r2, uint32_t& r3,
                                      uint32_t addr) {
    asm volatile("ldmatrix.sync.aligned.m8n8.x4.shared.b16 {%0,%1,%2,%3}, [%4];"
                 : "=r"(r0), "=r"(r1), "=r"(r2), "=r"(r3) : "r"(addr));
}

// bf16 mma: D(16x8,f32) += A(16x16,bf16) * B(16x8,bf16)
__device__ __forceinline__ void mma_bf16(float c[4], const uint32_t a[4], const uint32_t b[2]) {
    asm volatile(
        "mma.sync.aligned.m16n8k16.row.col.f32.bf16.bf16.f32 "
        "{%0,%1,%2,%3}, {%4,%5,%6,%7}, {%8,%9}, {%0,%1,%2,%3};"
        : "+f"(c[0]), "+f"(c[1]), "+f"(c[2]), "+f"(c[3])
        : "r"(a[0]), "r"(a[1]), "r"(a[2]), "r"(a[3]), "r"(b[0]), "r"(b[1]));
}

// split two fp32 into packed bf16 hi-pair and lo-pair (v0 -> low 16 bits)
__device__ __forceinline__ void split2(float v0, float v1, uint32_t& hp, uint32_t& lp) {
    __nv_bfloat162 hh, ll;
    hh.x = __float2bfloat16_rn(v0);
    hh.y = __float2bfloat16_rn(v1);
    ll.x = __float2bfloat16_rn(v0 - __bfloat162float(hh.x));
    ll.y = __float2bfloat16_rn(v1 - __bfloat162float(hh.y));
    hp = *reinterpret_cast<uint32_t*>(&hh);
    lp = *reinterpret_cast<uint32_t*>(&ll);
}

// ---------------- fused fp32 -> bf16 hi/lo conversion (ONE launch) ----------------
__global__ void __launch_bounds__(256) cvt_all_kernel(
    const float* __restrict__ q, const float* __restrict__ k, const float* __restrict__ v,
    const float* __restrict__ Wq, const float* __restrict__ Wk,
    const float* __restrict__ Wv, const float* __restrict__ Wo,
    uint32_t* qh, uint32_t* ql, uint32_t* kh, uint32_t* kl, uint32_t* vh, uint32_t* vl,
    uint32_t* Wqh, uint32_t* Wql, uint32_t* Wkh, uint32_t* Wkl,
    uint32_t* Wvh, uint32_t* Wvl, uint32_t* Woh, uint32_t* Wol)
{
    const int z = blockIdx.y;
    const float* in;
    uint32_t *h, *l;
    int n4;
    const int nAct4 = MT * D_MODEL / 4, nW4 = D_MODEL * D_MODEL / 4;
    switch (z) {
        case 0: in = q;  h = qh;  l = ql;  n4 = nAct4; break;
        case 1: in = k;  h = kh;  l = kl;  n4 = nAct4; break;
        case 2: in = v;  h = vh;  l = vl;  n4 = nAct4; break;
        case 3: in = Wq; h = Wqh; l = Wql; n4 = nW4;   break;
        case 4: in = Wk; h = Wkh; l = Wkl; n4 = nW4;   break;
        case 5: in = Wv; h = Wvh; l = Wvl; n4 = nW4;   break;
        default: in = Wo; h = Woh; l = Wol; n4 = nW4;  break;
    }
    int i = blockIdx.x * blockDim.x + threadIdx.x;
    const int stride = gridDim.x * blockDim.x;
    for (; i < n4; i += stride) {
        float4 x = ((const float4*)in)[i];
        uint32_t h0, l0, h1, l1;
        split2(x.x, x.y, h0, l0);
        split2(x.z, x.w, h1, l1);
        ((uint2*)h)[i] = make_uint2(h0, h1);
        ((uint2*)l)[i] = make_uint2(l0, l1);
    }
}

// ---------------- bf16x3 GEMM: C = A*B^T + bias ----------------
// CTA tile 128(M) x 64(N), kchunk 32, 8 warps (warp tile 32x32), 2 CTAs/SM.
#define GST 20                       // smem row stride (u32)
#define GTA (128 * GST)              // A tile u32 (2560)
#define GTB (64 * GST)               // B tile u32 (1280)
#define GBUF (2 * GTA + 2 * GTB)     // Ah, Al, Bh, Bl = 7680 u32
#define GEMM_SMEM (2 * GBUF * 4)     // 61440 B

__global__ void __launch_bounds__(256, 2) gemm_bf16x3_kernel(
    const uint32_t* __restrict__ Ah, const uint32_t* __restrict__ Al,
    const uint32_t* __restrict__ Bh, const uint32_t* __restrict__ Bl,
    const float* __restrict__ bias,
    float* __restrict__ Cf, uint32_t* __restrict__ Ch, uint32_t* __restrict__ Cl,
    int M, int N, int K, int mode)
{
    extern __shared__ uint32_t su[];
    const uint32_t smb = smem_u32(su);
    const int tid = threadIdx.x;
    const int wid = tid >> 5, lane = tid & 31;
    const int g = lane >> 2, t4 = lane & 3;
    const int qm = lane >> 3, rm = lane & 7;
    const int bm = blockIdx.y * 128, bn = blockIdx.x * 64;
    const int wm = (wid >> 1) * 32, wn = (wid & 1) * 32;
    const int KW = K >> 1;

    // tensor smem offsets within one buffer (u32)
    const int tOff[4] = {0, GTA, 2 * GTA, 2 * GTA + GTB};

    // loader: 1536 cp16 units; rows 0..127 Ah, 128..255 Al, 256..319 Bh, 320..383 Bl
    uint32_t soff[6];
    const uint32_t* gptr[6];
    #pragma unroll
    for (int it = 0; it < 6; it++) {
        int u = tid + 256 * it;
        int r = u >> 2, seg = (u & 3) * 4;
        int t, rr;
        if (r < 128)      { t = 0; rr = r; }
        else if (r < 256) { t = 1; rr = r - 128; }
        else if (r < 320) { t = 2; rr = r - 256; }
        else              { t = 3; rr = r - 320; }
        soff[it] = (uint32_t)(tOff[t] + rr * GST + seg);
        const uint32_t* base = (t == 0) ? Ah : (t == 1) ? Al : (t == 2) ? Bh : Bl;
        int grow = (t < 2) ? (bm + rr) : (bn + rr);
        gptr[it] = base + (size_t)grow * KW + seg;
    }

    float c[2][4][4];
    #pragma unroll
    for (int i = 0; i < 2; i++)
        #pragma unroll
        for (int j = 0; j < 4; j++)
            #pragma unroll
            for (int e = 0; e < 4; e++) c[i][j][e] = 0.f;

    auto load_chunk = [&](int ck, int buf) {
        uint32_t bb = smb + (uint32_t)(buf * GBUF) * 4u;
        #pragma unroll
        for (int it = 0; it < 6; it++)
            cp16(bb + soff[it] * 4u, gptr[it] + ck * 16);
    };

    // ldmatrix lane bases (u32 units within a tile)
    const int aLane = (wm + (qm & 1) * 8 + rm) * GST + (qm >> 1) * 4;
    const int bLane = (wn + (qm >> 1) * 8 + rm) * GST + (qm & 1) * 4;

    const int nck = K / 32;
    load_chunk(0, 0); cp_commit();

    for (int ck = 0; ck < nck; ck++) {
        cp_wait<0>();
        __syncthreads();
        if (ck + 1 < nck) { load_chunk(ck + 1, (ck + 1) & 1); cp_commit(); }

        const uint32_t bufA = smb + (uint32_t)((ck & 1) * GBUF) * 4u;
        const uint32_t sAhA = bufA;
        const uint32_t sAlA = bufA + (uint32_t)GTA * 4u;
        const uint32_t sBhA = bufA + (uint32_t)(2 * GTA) * 4u;
        const uint32_t sBlA = bufA + (uint32_t)(2 * GTA + GTB) * 4u;

        #pragma unroll
        for (int ks = 0; ks < 2; ks++) {
            uint32_t ah[2][4], al[2][4], bh[4][2], bl[4][2];
            #pragma unroll
            for (int i = 0; i < 2; i++) {
                uint32_t off = (uint32_t)(aLane + i * 16 * GST + ks * 8) * 4u;
                ldsm4(ah[i][0], ah[i][1], ah[i][2], ah[i][3], sAhA + off);
                ldsm4(al[i][0], al[i][1], al[i][2], al[i][3], sAlA + off);
            }
            #pragma unroll
            for (int jp = 0; jp < 2; jp++) {
                uint32_t off = (uint32_t)(bLane + jp * 16 * GST + ks * 8) * 4u;
                ldsm4(bh[2 * jp][0], bh[2 * jp][1], bh[2 * jp + 1][0], bh[2 * jp + 1][1],
                      sBhA + off);
                ldsm4(bl[2 * jp][0], bl[2 * jp][1], bl[2 * jp + 1][0], bl[2 * jp + 1][1],
                      sBlA + off);
            }
            #pragma unroll
            for (int i = 0; i < 2; i++)
                #pragma unroll
                for (int j = 0; j < 4; j++) {
                    mma_bf16(c[i][j], ah[i], bh[j]);
                    mma_bf16(c[i][j], ah[i], bl[j]);
                    mma_bf16(c[i][j], al[i], bh[j]);
                }
        }
        __syncthreads();
    }

    // epilogue
    if (mode == 0) {
        #pragma unroll
        for (int j = 0; j < 4; j++) {
            int col = bn + wn + 8 * j + 2 * t4;
            float b0 = bias[col], b1 = bias[col + 1];
            #pragma unroll
            for (int i = 0; i < 2; i++) {
                int row = bm + wm + 16 * i + g;
                *(float2*)&Cf[(size_t)row * N + col] =
                    make_float2(c[i][j][0] + b0, c[i][j][1] + b1);
                *(float2*)&Cf[(size_t)(row + 8) * N + col] =
                    make_float2(c[i][j][2] + b0, c[i][j][3] + b1);
            }
        }
    } else {
        const int NW = N >> 1;
        #pragma unroll
        for (int j = 0; j < 4; j++) {
            int col = bn + wn + 8 * j + 2 * t4;
            int ncol = (col >> 1);
            float b0 = bias[col], b1 = bias[col + 1];
            #pragma unroll
            for (int i = 0; i < 2; i++) {
                int row = bm + wm + 16 * i + g;
                uint32_t hp_, lp_;
                split2(c[i][j][0] + b0, c[i][j][1] + b1, hp_, lp_);
                Ch[(size_t)row * NW + ncol] = hp_;
                Cl[(size_t)row * NW + ncol] = lp_;
                split2(c[i][j][2] + b0, c[i][j][3] + b1, hp_, lp_);
                Ch[(size_t)(row + 8) * NW + ncol] = hp_;
                Cl[(size_t)(row + 8) * NW + ncol] = lp_;
            }
        }
    }
}

// ---------------- V transpose: [token][dpair] -> per (b,h): [d][keypair] ----------------
__global__ void __launch_bounds__(256) vtrans_kernel(
    const uint32_t* __restrict__ Vh, const uint32_t* __restrict__ Vl,
    uint32_t* __restrict__ Vth, uint32_t* __restrict__ Vtl)
{
    __shared__ uint32_t sh[64 * 32], sl[64 * 32];
    const int tid = threadIdx.x;
    const int kb = blockIdx.x, h = blockIdx.y, b = blockIdx.z;
    const size_t tokbase = (size_t)b * SEQ + kb * 64;
    const int hp = h * 32;

    #pragma unroll
    for (int m = 0; m < 8; m++) {
        int idx = tid + 256 * m;        // 0..2047
        int row = idx >> 5, col = idx & 31;
        sh[idx] = Vh[(tokbase + row) * KU + hp + col];
        sl[idx] = Vl[(tokbase + row) * KU + hp + col];
    }
    __syncthreads();

    const size_t obase = ((size_t)(b * NH + h) * DK) * (SEQ / 2) + kb * 32;
    #pragma unroll
    for (int m = 0; m < 8; m++) {
        int idx = tid + 256 * m;
        int d = idx >> 5, kp = idx & 31;
        int sel = (d & 1) * 16;
        uint32_t h0 = (sh[(2 * kp) * 32 + (d >> 1)] >> sel) & 0xffffu;
        uint32_t h1 = (sh[(2 * kp + 1) * 32 + (d >> 1)] >> sel) & 0xffffu;
        uint32_t l0 = (sl[(2 * kp) * 32 + (d >> 1)] >> sel) & 0xffffu;
        uint32_t l1 = (sl[(2 * kp + 1) * 32 + (d >> 1)] >> sel) & 0xffffu;
        Vth[obase + (size_t)d * (SEQ / 2) + kp] = h0 | (h1 << 16);
        Vtl[obase + (size_t)d * (SEQ / 2) + kp] = l0 | (l1 << 16);
    }
}

// ---------------- attention (bf16x3 mma, P kept in registers) ----------------
#define AST 36
#define KVT (64 * AST)                 // 2304 u32
#define KVBUF (4 * KVT)                // 9216 u32
#define ATTN_SMEM (2 * KVBUF * 4)      // 73728 B
#define SM_C 0.18033688f               // 0.125 * log2(e)

__global__ void __launch_bounds__(256, 1) attn_bf16_kernel(
    const uint32_t* __restrict__ Qh, const uint32_t* __restrict__ Ql,
    const uint32_t* __restrict__ Kh, const uint32_t* __restrict__ Kl,
    const uint32_t* __restrict__ Vth, const uint32_t* __restrict__ Vtl,
    uint32_t* __restrict__ Xh, uint32_t* __restrict__ Xl)
{
    extern __shared__ uint32_t su[];
    const uint32_t smb = smem_u32(su);
    const int tid = threadIdx.x;
    const int wid = tid >> 5, lane = tid & 31;
    const int g = lane >> 2, t4 = lane & 3;
    const int qm = lane >> 3, rm = lane & 7;
    const int qblk = blockIdx.x, h = blockIdx.y, b = blockIdx.z;
    const int hp = h * 32;
    const size_t tok0 = (size_t)b * SEQ;
    const int q0 = qblk * 128;
    const size_t vbase = ((size_t)(b * NH + h) * DK) * (SEQ / 2);

    // preload Q fragments (reused for all K-tiles)
    uint32_t aqh[4][4], aql[4][4];
    {
        const size_t r0 = (tok0 + q0 + wid * 16 + g) * KU + hp;
        const size_t r8 = r0 + 8 * KU;
        #pragma unroll
        for (int ks = 0; ks < 4; ks++) {
            int cc = ks * 8 + t4;
            aqh[ks][0] = Qh[r0 + cc];     aqh[ks][1] = Qh[r8 + cc];
            aqh[ks][2] = Qh[r0 + cc + 4]; aqh[ks][3] = Qh[r8 + cc + 4];
            aql[ks][0] = Ql[r0 + cc];     aql[ks][1] = Ql[r8 + cc];
            aql[ks][2] = Ql[r0 + cc + 4]; aql[ks][3] = Ql[r8 + cc + 4];
        }
    }

    float O[8][4];
    #pragma unroll
    for (int j = 0; j < 8; j++)
        #pragma unroll
        for (int e = 0; e < 4; e++) O[j][e] = 0.f;
    float m0 = -1e30f, m1 = -1e30f, l0 = 0.f, l1 = 0.f;

    auto tile_cp = [&](int kt, int buf) {
        uint32_t bb = smb + (uint32_t)buf * KVBUF * 4u;
        #pragma unroll
        for (int hh = 0; hh < 2; hh++) {
            int u = tid + 256 * hh;         // 0..511
            int row = u >> 3, seg = (u & 7) * 4;
            const size_t ktok = (tok0 + (size_t)kt * 64 + row) * KU + hp + seg;
            cp16(bb + (uint32_t)(row * AST + seg) * 4u, Kh + ktok);
            cp16(bb + (uint32_t)(KVT + row * AST + seg) * 4u, Kl + ktok);
            const size_t vpos = vbase + (size_t)row * (SEQ / 2) + (size_t)kt * 32 + seg;
            cp16(bb + (uint32_t)(2 * KVT + row * AST + seg) * 4u, Vth + vpos);
            cp16(bb + (uint32_t)(3 * KVT + row * AST + seg) * 4u, Vtl + vpos);
        }
    };

    // ldmatrix lane base for K / Vt B-fragments (u32 units)
    const int kvLane = ((qm >> 1) * 8 + rm) * AST + (qm & 1) * 4;

    tile_cp(0, 0); cp_commit();

    const int NT = SEQ / 64;   // 32
    for (int kt = 0; kt < NT; kt++) {
        cp_wait<0>();
        __syncthreads();
        if (kt + 1 < NT) { tile_cp(kt + 1, (kt + 1) & 1); cp_commit(); }

        const uint32_t bufA = smb + (uint32_t)((kt & 1) * KVBUF) * 4u;
        const uint32_t sKhA = bufA;
        const uint32_t sKlA = bufA + KVT * 4u;
        const uint32_t sVhA = bufA + 2u * KVT * 4u;
        const uint32_t sVlA = bufA + 3u * KVT * 4u;

        // ---- S = Q K^T (bf16x3) ----
        float s[8][4];
        #pragma unroll
        for (int j = 0; j < 8; j++)
            #pragma unroll
            for (int e = 0; e < 4; e++) s[j][e] = 0.f;

        #pragma unroll
        for (int ks = 0; ks < 4; ks++) {
            uint32_t bh[8][2], bl[8][2];
            #pragma unroll
            for (int jp = 0; jp < 4; jp++) {
                uint32_t off = (uint32_t)(kvLane + jp * 16 * AST + ks * 8) * 4u;
                ldsm4(bh[2 * jp][0], bh[2 * jp][1], bh[2 * jp + 1][0], bh[2 * jp + 1][1],
                      sKhA + off);
                ldsm4(bl[2 * jp][0], bl[2 * jp][1], bl[2 * jp + 1][0], bl[2 * jp + 1][1],
                      sKlA + off);
            }
            #pragma unroll
            for (int j = 0; j < 8; j++) {
                mma_bf16(s[j], aqh[ks], bh[j]);
                mma_bf16(s[j], aqh[ks], bl[j]);
                mma_bf16(s[j], aql[ks], bh[j]);
            }
        }

        // ---- online softmax in exp2 domain ----
        float mx0 = -1e30f, mx1 = -1e30f;
        #pragma unroll
        for (int j = 0; j < 8; j++) {
            mx0 = fmaxf(mx0, fmaxf(s[j][0], s[j][1]));
            mx1 = fmaxf(mx1, fmaxf(s[j][2], s[j][3]));
        }
        mx0 = fmaxf(mx0, __shfl_xor_sync(0xffffffffu, mx0, 1));
        mx0 = fmaxf(mx0, __shfl_xor_sync(0xffffffffu, mx0, 2));
        mx1 = fmaxf(mx1, __shfl_xor_sync(0xffffffffu, mx1, 1));
        mx1 = fmaxf(mx1, __shfl_xor_sync(0xffffffffu, mx1, 2));

        float nm0 = fmaxf(m0, mx0), nm1 = fmaxf(m1, mx1);
        float cr0 = exp2f((m0 - nm0) * SM_C), cr1 = exp2f((m1 - nm1) * SM_C);
        m0 = nm0; m1 = nm1;

        float sum0 = 0.f, sum1 = 0.f;
        #pragma unroll
        for (int j = 0; j < 8; j++) {
            s[j][0] = exp2f((s[j][0] - m0) * SM_C);
            s[j][1] = exp2f((s[j][1] - m0) * SM_C);
            s[j][2] = exp2f((s[j][2] - m1) * SM_C);
            s[j][3] = exp2f((s[j][3] - m1) * SM_C);
            sum0 += s[j][0] + s[j][1];
            sum1 += s[j][2] + s[j][3];
        }
        sum0 += __shfl_xor_sync(0xffffffffu, sum0, 1);
        sum0 += __shfl_xor_sync(0xffffffffu, sum0, 2);
        sum1 += __shfl_xor_sync(0xffffffffu, sum1, 1);
        sum1 += __shfl_xor_sync(0xffffffffu, sum1, 2);
        l0 = l0 * cr0 + sum0;
        l1 = l1 * cr1 + sum1;

        #pragma unroll
        for (int j = 0; j < 8; j++) {
            O[j][0] *= cr0; O[j][1] *= cr0; O[j][2] *= cr1; O[j][3] *= cr1;
        }

        // ---- build P A-fragments in registers (FA-2 layout identity) ----
        // A-frag for k-chunk ks (keys 16ks..16ks+15):
        //   a0 = (row g,   keys 16ks+2t4, +1) = pack(s[2ks][0],   s[2ks][1])
        //   a1 = (row g+8, same keys)         = pack(s[2ks][2],   s[2ks][3])
        //   a2 = (row g,   keys 16ks+8+2t4)   = pack(s[2ks+1][0], s[2ks+1][1])
        //   a3 = (row g+8, same)              = pack(s[2ks+1][2], s[2ks+1][3])
        uint32_t pah[4][4], pal[4][4];
        #pragma unroll
        for (int ks = 0; ks < 4; ks++) {
            split2(s[2 * ks][0],     s[2 * ks][1],     pah[ks][0], pal[ks][0]);
            split2(s[2 * ks][2],     s[2 * ks][3],     pah[ks][1], pal[ks][1]);
            split2(s[2 * ks + 1][0], s[2 * ks + 1][1], pah[ks][2], pal[ks][2]);
            split2(s[2 * ks + 1][2], s[2 * ks + 1][3], pah[ks][3], pal[ks][3]);
        }

        // ---- O += P V (bf16x3) ----
        #pragma unroll
        for (int ks = 0; ks < 4; ks++) {
            uint32_t bh[8][2], bl[8][2];
            #pragma unroll
            for (int jp = 0; jp < 4; jp++) {
                uint32_t off = (uint32_t)(kvLane + jp * 16 * AST + ks * 8) * 4u;
                ldsm4(bh[2 * jp][0], bh[2 * jp][1], bh[2 * jp + 1][0], bh[2 * jp + 1][1],
                      sVhA + off);
                ldsm4(bl[2 * jp][0], bl[2 * jp][1], bl[2 * jp + 1][0], bl[2 * jp + 1][1],
                      sVlA + off);
            }
            #pragma unroll
            for (int j = 0; j < 8; j++) {
                mma_bf16(O[j], pah[ks], bh[j]);
                mma_bf16(O[j], pah[ks], bl[j]);
                mma_bf16(O[j], pal[ks], bh[j]);
            }
        }
    }

    // ---- epilogue: normalize, split, store X ----
    {
        float i0 = 1.f / l0, i1 = 1.f / l1;
        const size_t r0 = (tok0 + q0 + wid * 16 + g) * KU + hp;
        const size_t r8 = r0 + 8 * KU;
        #pragma unroll
        for (int j = 0; j < 8; j++) {
            uint32_t hp_, lp_;
            split2(O[j][0] * i0, O[j][1] * i0, hp_, lp_);
            Xh[r0 + 4 * j + t4] = hp_;
            Xl[r0 + 4 * j + t4] = lp_;
            split2(O[j][2] * i1, O[j][3] * i1, hp_, lp_);
            Xh[r8 + 4 * j + t4] = hp_;
            Xl[r8 + 4 * j + t4] = lp_;
        }
    }
}

// ---------------- launch ----------------
extern "C" void kernel_launch(void* const* d_in, const int* in_sizes, int n_in,
                              void* d_out, int out_size)
{
    const float* q  = (const float*)d_in[0];
    const float* k  = (const float*)d_in[1];
    const float* v  = (const float*)d_in[2];
    const float* Wq = (const float*)d_in[3];
    const float* bq = (const float*)d_in[4];
    const float* Wk = (const float*)d_in[5];
    const float* bk = (const float*)d_in[6];
    const float* Wv = (const float*)d_in[7];
    const float* bv = (const float*)d_in[8];
    const float* Wo = (const float*)d_in[9];
    const float* bo = (const float*)d_in[10];
    float* out = (float*)d_out;

    uint32_t *qh, *ql, *kh, *kl, *vh, *vl;
    uint32_t *Wqh, *Wql, *Wkh, *Wkl, *Wvh, *Wvl, *Woh, *Wol;
    uint32_t *Qh, *Ql, *Kh, *Kl, *Vh, *Vl, *Vth, *Vtl, *Xh, *Xl;
    cudaGetSymbolAddress((void**)&qh, g_qh);   cudaGetSymbolAddress((void**)&ql, g_ql);
    cudaGetSymbolAddress((void**)&kh, g_kh);   cudaGetSymbolAddress((void**)&kl, g_kl);
    cudaGetSymbolAddress((void**)&vh, g_vh);   cudaGetSymbolAddress((void**)&vl, g_vl);
    cudaGetSymbolAddress((void**)&Wqh, g_Wqh); cudaGetSymbolAddress((void**)&Wql, g_Wql);
    cudaGetSymbolAddress((void**)&Wkh, g_Wkh); cudaGetSymbolAddress((void**)&Wkl, g_Wkl);
    cudaGetSymbolAddress((void**)&Wvh, g_Wvh); cudaGetSymbolAddress((void**)&Wvl, g_Wvl);
    cudaGetSymbolAddress((void**)&Woh, g_Woh); cudaGetSymbolAddress((void**)&Wol, g_Wol);
    cudaGetSymbolAddress((void**)&Qh, g_Qh);   cudaGetSymbolAddress((void**)&Ql, g_Ql);
    cudaGetSymbolAddress((void**)&Kh, g_Kh);   cudaGetSymbolAddress((void**)&Kl, g_Kl);
    cudaGetSymbolAddress((void**)&Vh, g_Vh);   cudaGetSymbolAddress((void**)&Vl, g_Vl);
    cudaGetSymbolAddress((void**)&Vth, g_Vth); cudaGetSymbolAddress((void**)&Vtl, g_Vtl);
    cudaGetSymbolAddress((void**)&Xh, g_Xh);   cudaGetSymbolAddress((void**)&Xl, g_Xl);

    cudaFuncSetAttribute(gemm_bf16x3_kernel,
                         cudaFuncAttributeMaxDynamicSharedMemorySize, GEMM_SMEM);
    cudaFuncSetAttribute(attn_bf16_kernel,
                         cudaFuncAttributeMaxDynamicSharedMemorySize, ATTN_SMEM);

    // launch 1: fused conversions
    cvt_all_kernel<<<dim3(256, 7), 256>>>(q, k, v, Wq, Wk, Wv, Wo,
                                          qh, ql, kh, kl, vh, vl,
                                          Wqh, Wql, Wkh, Wkl, Wvh, Wvl, Woh, Wol);

    // launches 2-4: projections (CTA 128x64 -> grid (16, 32))
    dim3 ggrid(D_MODEL / 64, MT / 128);
    gemm_bf16x3_kernel<<<ggrid, 256, GEMM_SMEM>>>(qh, ql, Wqh, Wql, bq,
                                                  nullptr, Qh, Ql, MT, D_MODEL, D_MODEL, 1);
    gemm_bf16x3_kernel<<<ggrid, 256, GEMM_SMEM>>>(kh, kl, Wkh, Wkl, bk,
                                                  nullptr, Kh, Kl, MT, D_MODEL, D_MODEL, 1);
    gemm_bf16x3_kernel<<<ggrid, 256, GEMM_SMEM>>>(vh, vl, Wvh, Wvl, bv,
                                                  nullptr, Vh, Vl, MT, D_MODEL, D_MODEL, 1);

    // launch 5: V transpose
    dim3 tgrid(SEQ / 64, NH, BATCH);          // (32, 16, 2)
    vtrans_kernel<<<tgrid, 256>>>(Vh, Vl, Vth, Vtl);

    // launch 6: attention
    dim3 agrid(SEQ / 128, NH, BATCH);         // (16, 16, 2)
    attn_bf16_kernel<<<agrid, 256, ATTN_SMEM>>>(Qh, Ql, Kh, Kl, Vth, Vtl, Xh, Xl);

    // launch 7: output projection
    gemm_bf16x3_kernel<<<ggrid, 256, GEMM_SMEM>>>(Xh, Xl, Woh, Wol, bo,
                                                  out, nullptr, nullptr, MT, D_MODEL, D_MODEL, 0);
}